// round 5
// baseline (speedup 1.0000x reference)
#include <cuda_runtime.h>
#include <math.h>

#define N_NODES 100000
#define N_EDGES 1000000
#define N_GRAPHS 128
#define HD 64
#define BN_EPS 1e-5f

// ---------------- scratch (device globals; no allocation allowed) ----------------
__device__ __align__(16) int   g_rowptr[N_NODES + 1];
__device__ __align__(16) int   g_cursor[N_NODES];
__device__ __align__(16) int   g_deg[N_NODES];
__device__ __align__(16) int   g_csrsrc[N_EDGES];
__device__ __align__(16) float g_h[N_NODES * HD];
__device__ __align__(16) float g_y[N_NODES * HD];
__device__ __align__(16) float g_pool[N_GRAPHS * HD];
__device__ __align__(16) int   g_cnt[N_GRAPHS];

// ---------------- helpers ----------------
__device__ __forceinline__ unsigned f2tf(float f) {
    unsigned u;
    asm("cvt.rna.tf32.f32 %0, %1;" : "=r"(u) : "f"(f));
    return u;
}
__device__ __forceinline__ void mma_tf32(float* c, const unsigned* a,
                                         unsigned b0, unsigned b1) {
    asm("mma.sync.aligned.m16n8k8.row.col.f32.tf32.tf32.f32 "
        "{%0,%1,%2,%3},{%4,%5,%6,%7},{%8,%9},{%0,%1,%2,%3};"
        : "+f"(c[0]), "+f"(c[1]), "+f"(c[2]), "+f"(c[3])
        : "r"(a[0]), "r"(a[1]), "r"(a[2]), "r"(a[3]), "r"(b0), "r"(b1));
}

// ---------------- CSR build ----------------
__global__ void k_init() {
    int i = blockIdx.x * blockDim.x + threadIdx.x;
    if (i < N_NODES) g_deg[i] = 0;
    if (i < N_GRAPHS * HD) g_pool[i] = 0.f;
    if (i < N_GRAPHS) g_cnt[i] = 0;
}

__global__ void k_count(const int* __restrict__ ei,
                        const int* __restrict__ batch) {
    int e = blockIdx.x * blockDim.x + threadIdx.x;
    if (e < N_EDGES) atomicAdd(&g_deg[ei[N_EDGES + e]], 1);
    if (e < N_NODES) atomicAdd(&g_cnt[batch[e]], 1);
}

// single block, 1024 threads, 4 elements/thread: exclusive scan -> rowptr, cursor
__global__ void k_scan() {
    __shared__ int warpsum[32];
    int tid = threadIdx.x, lane = tid & 31, wid = tid >> 5;
    int carry = 0;
    if (tid == 0) g_rowptr[0] = 0;
    for (int base = 0; base < N_NODES; base += 4096) {
        int i0 = base + tid * 4;
        int4 v = make_int4(0, 0, 0, 0);
        if (i0 + 3 < N_NODES) {
            v = *(const int4*)&g_deg[i0];
        } else {
            if (i0 + 0 < N_NODES) v.x = g_deg[i0 + 0];
            if (i0 + 1 < N_NODES) v.y = g_deg[i0 + 1];
            if (i0 + 2 < N_NODES) v.z = g_deg[i0 + 2];
            if (i0 + 3 < N_NODES) v.w = g_deg[i0 + 3];
        }
        int s = v.x + v.y + v.z + v.w;
        int x = s;
        #pragma unroll
        for (int off = 1; off < 32; off <<= 1) {
            int t = __shfl_up_sync(0xffffffffu, x, off);
            if (lane >= off) x += t;
        }
        if (lane == 31) warpsum[wid] = x;
        __syncthreads();
        if (wid == 0) {
            int w = warpsum[lane];
            #pragma unroll
            for (int off = 1; off < 32; off <<= 1) {
                int t = __shfl_up_sync(0xffffffffu, w, off);
                if (lane >= off) w += t;
            }
            warpsum[lane] = w;
        }
        __syncthreads();
        int woff = (wid > 0) ? warpsum[wid - 1] : 0;
        int excl = carry + woff + (x - s);
        int p0 = excl + v.x, p1 = p0 + v.y, p2 = p1 + v.z, p3 = p2 + v.w;
        if (i0 + 0 < N_NODES) { g_cursor[i0 + 0] = excl; g_rowptr[i0 + 1] = p0; }
        if (i0 + 1 < N_NODES) { g_cursor[i0 + 1] = p0;   g_rowptr[i0 + 2] = p1; }
        if (i0 + 2 < N_NODES) { g_cursor[i0 + 2] = p1;   g_rowptr[i0 + 3] = p2; }
        if (i0 + 3 < N_NODES) { g_cursor[i0 + 3] = p2;   g_rowptr[i0 + 4] = p3; }
        carry += warpsum[31];
        __syncthreads();
    }
}

__global__ void k_scatter(const int* __restrict__ ei) {
    int e = blockIdx.x * blockDim.x + threadIdx.x;
    if (e >= N_EDGES) return;
    int d = ei[N_EDGES + e];
    int s = ei[e];
    int p = atomicAdd(&g_cursor[d], 1);
    g_csrsrc[p] = s;
}

// ---------------- layer-0 input GEMM: g_y[N,64] = x[N,128] @ W1_0[128,64] (TF32) ----
__global__ __launch_bounds__(256) void k_gemm0(const float* __restrict__ A,
                                               const float* __restrict__ W) {
    constexpr int K = 128;
    __shared__ unsigned sA[256 * 17];
    __shared__ unsigned sW[16 * 65];
    int tid = threadIdx.x;
    int wid = tid >> 5, lane = tid & 31;
    int tg = lane >> 2, tig = lane & 3;
    int row0 = blockIdx.x * 256;

    float c[2][8][4];
    #pragma unroll
    for (int mt = 0; mt < 2; mt++)
        #pragma unroll
        for (int nt = 0; nt < 8; nt++)
            #pragma unroll
            for (int j = 0; j < 4; j++) c[mt][nt][j] = 0.f;

    for (int ch = 0; ch < 8; ch++) {
        int kbase = ch * 16;
        #pragma unroll
        for (int i = 0; i < 4; i++) {
            int idx = tid + i * 256;
            int r = idx >> 2, c4 = idx & 3;
            int grow = row0 + r;
            float4 v = make_float4(0.f, 0.f, 0.f, 0.f);
            if (grow < N_NODES)
                v = *(const float4*)(A + (size_t)grow * K + kbase + c4 * 4);
            unsigned* p = &sA[r * 17 + c4 * 4];
            p[0] = f2tf(v.x); p[1] = f2tf(v.y); p[2] = f2tf(v.z); p[3] = f2tf(v.w);
        }
        {
            int k = tid >> 4, c4 = tid & 15;
            float4 v = *(const float4*)(W + (size_t)(kbase + k) * 64 + c4 * 4);
            unsigned* p = &sW[k * 65 + c4 * 4];
            p[0] = f2tf(v.x); p[1] = f2tf(v.y); p[2] = f2tf(v.z); p[3] = f2tf(v.w);
        }
        __syncthreads();
        #pragma unroll
        for (int ks = 0; ks < 2; ks++) {
            int ko = ks * 8;
            unsigned a[2][4];
            #pragma unroll
            for (int mt = 0; mt < 2; mt++) {
                int rr = wid * 32 + mt * 16 + tg;
                a[mt][0] = sA[rr * 17 + ko + tig];
                a[mt][1] = sA[(rr + 8) * 17 + ko + tig];
                a[mt][2] = sA[rr * 17 + ko + tig + 4];
                a[mt][3] = sA[(rr + 8) * 17 + ko + tig + 4];
            }
            #pragma unroll
            for (int nt = 0; nt < 8; nt++) {
                unsigned b0 = sW[(ko + tig) * 65 + nt * 8 + tg];
                unsigned b1 = sW[(ko + tig + 4) * 65 + nt * 8 + tg];
                mma_tf32(c[0][nt], a[0], b0, b1);
                mma_tf32(c[1][nt], a[1], b0, b1);
            }
        }
        __syncthreads();
    }
    #pragma unroll
    for (int mt = 0; mt < 2; mt++) {
        int row = row0 + wid * 32 + mt * 16 + tg;
        #pragma unroll
        for (int half = 0; half < 2; half++) {
            int r = row + half * 8;
            if (r < N_NODES) {
                #pragma unroll
                for (int nt = 0; nt < 8; nt++) {
                    int col = nt * 8 + tig * 2;
                    *(float2*)(g_y + (size_t)r * HD + col) =
                        make_float2(c[mt][nt][half * 2 + 0], c[mt][nt][half * 2 + 1]);
                }
            }
        }
    }
}

// ---------------- fused layer kernel ----------------
// u = in[row] + sum_{e: dst=row} in[src]          (gather, 64-dim)
// v = HAS_W1 ? u @ W1 : u
// a = relu(BN(v))
// o = relu(a @ W2)
// POOL ? atomicAdd into g_pool : store o to out buffer
// IN_Y: in = g_y, out = g_h; else in = g_h, out = g_y.
template <bool HAS_W1, bool POOL, bool IN_Y>
__global__ __launch_bounds__(128) void k_layer(const float* __restrict__ W1,
                                               const float* __restrict__ W2,
                                               const float* __restrict__ gam,
                                               const float* __restrict__ bet,
                                               const float* __restrict__ mea,
                                               const float* __restrict__ var,
                                               const int* __restrict__ batch) {
    __shared__ unsigned sA[128 * 68];   // 128 rows x 64 cols, stride 68
    __shared__ unsigned sW[16 * 68];    // one 16-k chunk of W
    __shared__ float sScale[64], sShift[64];

    const float* inb = IN_Y ? (const float*)g_y : (const float*)g_h;
    float* outb = IN_Y ? g_h : g_y;

    int tid = threadIdx.x, wid = tid >> 5, lane = tid & 31;
    int tg = lane >> 2, tig = lane & 3;
    int row0 = blockIdx.x * 128;

    if (tid < 64) {
        float sc = rsqrtf(var[tid] + BN_EPS) * gam[tid];
        sScale[tid] = sc;
        sShift[tid] = bet[tid] - mea[tid] * sc;
    }
    __syncthreads();

    // ---- gather phase: warp handles its own 32 rows ----
    {
        const float2* yv = (const float2*)inb;
        float scl = sScale[2 * lane], sht = sShift[2 * lane];
        float scl1 = sScale[2 * lane + 1], sht1 = sShift[2 * lane + 1];
        for (int j = 0; j < 32; j++) {
            int lr = wid * 32 + j;
            int gn = row0 + lr;
            float2 acc = make_float2(0.f, 0.f);
            if (gn < N_NODES) {
                acc = yv[(size_t)gn * 32 + lane];
                int beg = g_rowptr[gn], end = g_rowptr[gn + 1];
                for (int base = beg; base < end; base += 32) {
                    int n = end - base;
                    if (n > 32) n = 32;
                    int idx = (lane < n) ? g_csrsrc[base + lane] : 0;
                    int t = 0;
                    for (; t + 4 <= n; t += 4) {
                        int s0 = __shfl_sync(0xffffffffu, idx, t + 0);
                        int s1 = __shfl_sync(0xffffffffu, idx, t + 1);
                        int s2 = __shfl_sync(0xffffffffu, idx, t + 2);
                        int s3 = __shfl_sync(0xffffffffu, idx, t + 3);
                        float2 v0 = yv[(size_t)s0 * 32 + lane];
                        float2 v1 = yv[(size_t)s1 * 32 + lane];
                        float2 v2 = yv[(size_t)s2 * 32 + lane];
                        float2 v3 = yv[(size_t)s3 * 32 + lane];
                        acc.x += (v0.x + v1.x) + (v2.x + v3.x);
                        acc.y += (v0.y + v1.y) + (v2.y + v3.y);
                    }
                    for (; t < n; t++) {
                        int s = __shfl_sync(0xffffffffu, idx, t);
                        float2 v = yv[(size_t)s * 32 + lane];
                        acc.x += v.x;
                        acc.y += v.y;
                    }
                }
            }
            if (!HAS_W1) {  // BN + relu applied directly to u (layer 0 path)
                acc.x = fmaxf(fmaf(acc.x, scl, sht), 0.f);
                acc.y = fmaxf(fmaf(acc.y, scl1, sht1), 0.f);
            }
            uint2 tv;
            tv.x = f2tf(acc.x);
            tv.y = f2tf(acc.y);
            *(uint2*)&sA[lr * 68 + 2 * lane] = tv;
        }
    }

    float c[2][8][4];
    #pragma unroll
    for (int mt = 0; mt < 2; mt++)
        #pragma unroll
        for (int nt = 0; nt < 8; nt++)
            #pragma unroll
            for (int j = 0; j < 4; j++) c[mt][nt][j] = 0.f;

    if (HAS_W1) {
        // ---- GEMM1: v = u @ W1 ----
        for (int ch = 0; ch < 4; ch++) {
            __syncthreads();  // also aligns warps after gather / protects prev chunk
            {
                #pragma unroll
                for (int it = 0; it < 2; it++) {
                    int id = tid + it * 128;
                    int k = id >> 4, c4 = id & 15;
                    float4 v = *(const float4*)(W1 + (size_t)(ch * 16 + k) * 64 + c4 * 4);
                    unsigned* p = &sW[k * 68 + c4 * 4];
                    p[0] = f2tf(v.x); p[1] = f2tf(v.y); p[2] = f2tf(v.z); p[3] = f2tf(v.w);
                }
            }
            __syncthreads();
            #pragma unroll
            for (int ks = 0; ks < 2; ks++) {
                int ko = ks * 8;
                int kg = ch * 16 + ko;  // global k column in sA
                unsigned a[2][4];
                #pragma unroll
                for (int mt = 0; mt < 2; mt++) {
                    int rr = wid * 32 + mt * 16 + tg;
                    a[mt][0] = sA[rr * 68 + kg + tig];
                    a[mt][1] = sA[(rr + 8) * 68 + kg + tig];
                    a[mt][2] = sA[rr * 68 + kg + tig + 4];
                    a[mt][3] = sA[(rr + 8) * 68 + kg + tig + 4];
                }
                #pragma unroll
                for (int nt = 0; nt < 8; nt++) {
                    unsigned b0 = sW[(ko + tig) * 68 + nt * 8 + tg];
                    unsigned b1 = sW[(ko + tig + 4) * 68 + nt * 8 + tg];
                    mma_tf32(c[0][nt], a[0], b0, b1);
                    mma_tf32(c[1][nt], a[1], b0, b1);
                }
            }
        }
        // ---- BN + relu, write a back over own rows ----
        #pragma unroll
        for (int mt = 0; mt < 2; mt++) {
            int rlo = wid * 32 + mt * 16 + tg;
            #pragma unroll
            for (int nt = 0; nt < 8; nt++) {
                int col = nt * 8 + 2 * tig;
                float sc0 = sScale[col], sh0 = sShift[col];
                float sc1 = sScale[col + 1], sh1 = sShift[col + 1];
                uint2 lo, hi;
                lo.x = f2tf(fmaxf(fmaf(c[mt][nt][0], sc0, sh0), 0.f));
                lo.y = f2tf(fmaxf(fmaf(c[mt][nt][1], sc1, sh1), 0.f));
                hi.x = f2tf(fmaxf(fmaf(c[mt][nt][2], sc0, sh0), 0.f));
                hi.y = f2tf(fmaxf(fmaf(c[mt][nt][3], sc1, sh1), 0.f));
                *(uint2*)&sA[rlo * 68 + col] = lo;
                *(uint2*)&sA[(rlo + 8) * 68 + col] = hi;
            }
        }
        __syncwarp();
        // re-zero accumulators for GEMM2
        #pragma unroll
        for (int mt = 0; mt < 2; mt++)
            #pragma unroll
            for (int nt = 0; nt < 8; nt++)
                #pragma unroll
                for (int j = 0; j < 4; j++) c[mt][nt][j] = 0.f;
    }

    // ---- GEMM2: o = a @ W2 ----
    for (int ch = 0; ch < 4; ch++) {
        __syncthreads();
        {
            #pragma unroll
            for (int it = 0; it < 2; it++) {
                int id = tid + it * 128;
                int k = id >> 4, c4 = id & 15;
                float4 v = *(const float4*)(W2 + (size_t)(ch * 16 + k) * 64 + c4 * 4);
                unsigned* p = &sW[k * 68 + c4 * 4];
                p[0] = f2tf(v.x); p[1] = f2tf(v.y); p[2] = f2tf(v.z); p[3] = f2tf(v.w);
            }
        }
        __syncthreads();
        #pragma unroll
        for (int ks = 0; ks < 2; ks++) {
            int ko = ks * 8;
            int kg = ch * 16 + ko;
            unsigned a[2][4];
            #pragma unroll
            for (int mt = 0; mt < 2; mt++) {
                int rr = wid * 32 + mt * 16 + tg;
                a[mt][0] = sA[rr * 68 + kg + tig];
                a[mt][1] = sA[(rr + 8) * 68 + kg + tig];
                a[mt][2] = sA[rr * 68 + kg + tig + 4];
                a[mt][3] = sA[(rr + 8) * 68 + kg + tig + 4];
            }
            #pragma unroll
            for (int nt = 0; nt < 8; nt++) {
                unsigned b0 = sW[(ko + tig) * 68 + nt * 8 + tg];
                unsigned b1 = sW[(ko + tig + 4) * 68 + nt * 8 + tg];
                mma_tf32(c[0][nt], a[0], b0, b1);
                mma_tf32(c[1][nt], a[1], b0, b1);
            }
        }
    }

    // ---- epilogue: relu, store or pool ----
    #pragma unroll
    for (int mt = 0; mt < 2; mt++) {
        int row = row0 + wid * 32 + mt * 16 + tg;
        #pragma unroll
        for (int half = 0; half < 2; half++) {
            int r = row + half * 8;
            if (r < N_NODES) {
                int b = POOL ? batch[r] : 0;
                #pragma unroll
                for (int nt = 0; nt < 8; nt++) {
                    int col = nt * 8 + tig * 2;
                    float v0 = fmaxf(c[mt][nt][half * 2 + 0], 0.f);
                    float v1 = fmaxf(c[mt][nt][half * 2 + 1], 0.f);
                    if (POOL) {
                        atomicAdd(&g_pool[b * HD + col], v0);
                        atomicAdd(&g_pool[b * HD + col + 1], v1);
                    } else {
                        *(float2*)(outb + (size_t)r * HD + col) = make_float2(v0, v1);
                    }
                }
            }
        }
    }
}

// ---------------- final head: mean, lin1+relu, lin2+bias, log_softmax ----------------
__global__ void k_final(const float* __restrict__ lin1, const float* __restrict__ lin2,
                        const float* __restrict__ lb, float* __restrict__ out) {
    __shared__ float sL1[64 * 64];
    __shared__ float sL2[64 * 10];
    __shared__ float sB[10];
    int tid = threadIdx.x;
    for (int i = tid; i < 64 * 64; i += 128) sL1[i] = lin1[i];
    for (int i = tid; i < 64 * 10; i += 128) sL2[i] = lin2[i];
    if (tid < 10) sB[tid] = lb[tid];
    __syncthreads();
    if (tid < N_GRAPHS) {
        float cnt = (float)g_cnt[tid];
        if (cnt < 1.f) cnt = 1.f;
        float pooled[64];
        #pragma unroll
        for (int k = 0; k < 64; k++) pooled[k] = g_pool[tid * 64 + k] / cnt;
        float o[10];
        #pragma unroll
        for (int c = 0; c < 10; c++) o[c] = sB[c];
        for (int j = 0; j < 64; j++) {
            float z = 0.f;
            #pragma unroll
            for (int k = 0; k < 64; k++) z += pooled[k] * sL1[k * 64 + j];
            z = fmaxf(z, 0.f);
            #pragma unroll
            for (int c = 0; c < 10; c++) o[c] += z * sL2[j * 10 + c];
        }
        float mx = o[0];
        #pragma unroll
        for (int c = 1; c < 10; c++) mx = fmaxf(mx, o[c]);
        float se = 0.f;
        #pragma unroll
        for (int c = 0; c < 10; c++) se += expf(o[c] - mx);
        float lse = logf(se) + mx;
        #pragma unroll
        for (int c = 0; c < 10; c++) out[tid * 10 + c] = o[c] - lse;
    }
}

// ---------------- launch (kernel launches ONLY) ----------------
extern "C" void kernel_launch(void* const* d_in, const int* in_sizes, int n_in,
                              void* d_out, int out_size) {
    const float* x      = (const float*)d_in[0];
    const int*   ei     = (const int*)d_in[1];
    const int*   batch  = (const int*)d_in[2];
    const float* W1_0   = (const float*)d_in[3];
    const float* bn_g_0 = (const float*)d_in[4];
    const float* bn_b_0 = (const float*)d_in[5];
    const float* bn_m_0 = (const float*)d_in[6];
    const float* bn_v_0 = (const float*)d_in[7];
    const float* W2_0   = (const float*)d_in[8];
    const float* W1_r   = (const float*)d_in[9];
    const float* bn_g_r = (const float*)d_in[10];
    const float* bn_b_r = (const float*)d_in[11];
    const float* bn_m_r = (const float*)d_in[12];
    const float* bn_v_r = (const float*)d_in[13];
    const float* W2_r   = (const float*)d_in[14];
    const float* lin1   = (const float*)d_in[15];
    const float* lin2   = (const float*)d_in[16];
    const float* lin2b  = (const float*)d_in[17];
    float* out = (float*)d_out;

    const int TPB = 256;
    int gridNodes = (N_NODES + TPB - 1) / TPB;
    int gridEdges = (N_EDGES + TPB - 1) / TPB;
    int gridGemm0 = (N_NODES + 255) / 256;   // 391
    int gridLayer = (N_NODES + 127) / 128;   // 782

    // CSR build
    k_init<<<gridNodes, TPB>>>();
    k_count<<<gridEdges, TPB>>>(ei, batch);
    k_scan<<<1, 1024>>>();
    k_scatter<<<gridEdges, TPB>>>(ei);

    // layer 0: y = x @ W1_0 (K=128), then fused gather+BN+relu+W2
    k_gemm0<<<gridGemm0, TPB>>>(x, W1_0);
    k_layer<false, false, true><<<gridLayer, 128>>>(
        nullptr, W2_0, bn_g_0, bn_b_0, bn_m_0, bn_v_0, nullptr);      // g_y -> g_h

    // layers 1..2: fully fused (gather + W1 + BN + relu + W2 + relu)
    k_layer<true, false, false><<<gridLayer, 128>>>(
        W1_r + 0 * 4096, W2_r + 0 * 4096,
        bn_g_r + 0, bn_b_r + 0, bn_m_r + 0, bn_v_r + 0, nullptr);     // g_h -> g_y
    k_layer<true, false, true><<<gridLayer, 128>>>(
        W1_r + 1 * 4096, W2_r + 1 * 4096,
        bn_g_r + 64, bn_b_r + 64, bn_m_r + 64, bn_v_r + 64, nullptr); // g_y -> g_h

    // layer 3: fused + mean-pool accumulation epilogue (no h write)
    k_layer<true, true, false><<<gridLayer, 128>>>(
        W1_r + 2 * 4096, W2_r + 2 * 4096,
        bn_g_r + 128, bn_b_r + 128, bn_m_r + 128, bn_v_r + 128, batch); // g_h -> pool

    // head
    k_final<<<1, 128>>>(lin1, lin2, lin2b, out);
}

// round 6
// speedup vs baseline: 1.3204x; 1.3204x over previous
#include <cuda_runtime.h>
#include <cuda_fp16.h>
#include <math.h>

#define N_NODES 100000
#define N_EDGES 1000000
#define N_GRAPHS 128
#define HD 64
#define BN_EPS 1e-5f

// ---------------- scratch (device globals; no allocation allowed) ----------------
__device__ __align__(16) int    g_rowptr[N_NODES + 1];
__device__ __align__(16) int    g_cursor[N_NODES];
__device__ __align__(16) int    g_deg[N_NODES];
__device__ __align__(16) int    g_csrsrc[N_EDGES];
__device__ __align__(16) __half g_h[N_NODES * HD];
__device__ __align__(16) __half g_y[N_NODES * HD];
__device__ __align__(16) __half g_a[N_NODES * HD];
__device__ __align__(16) float  g_pool[N_GRAPHS * HD];
__device__ __align__(16) int    g_cnt[N_GRAPHS];

// ---------------- helpers ----------------
__device__ __forceinline__ unsigned f2tf(float f) {
    unsigned u;
    asm("cvt.rna.tf32.f32 %0, %1;" : "=r"(u) : "f"(f));
    return u;
}
__device__ __forceinline__ void mma_tf32(float* c, const unsigned* a,
                                         unsigned b0, unsigned b1) {
    asm("mma.sync.aligned.m16n8k8.row.col.f32.tf32.tf32.f32 "
        "{%0,%1,%2,%3},{%4,%5,%6,%7},{%8,%9},{%0,%1,%2,%3};"
        : "+f"(c[0]), "+f"(c[1]), "+f"(c[2]), "+f"(c[3])
        : "r"(a[0]), "r"(a[1]), "r"(a[2]), "r"(a[3]), "r"(b0), "r"(b1));
}

// ---------------- CSR build ----------------
__global__ void k_init() {
    int i = blockIdx.x * blockDim.x + threadIdx.x;
    if (i < N_NODES) g_deg[i] = 0;
    if (i < N_GRAPHS * HD) g_pool[i] = 0.f;
    if (i < N_GRAPHS) g_cnt[i] = 0;
}

__global__ void k_count(const int* __restrict__ ei,
                        const int* __restrict__ batch) {
    int e = blockIdx.x * blockDim.x + threadIdx.x;
    if (e < N_EDGES) atomicAdd(&g_deg[ei[N_EDGES + e]], 1);
    if (e < N_NODES) atomicAdd(&g_cnt[batch[e]], 1);
}

// single block, 1024 threads, 4 elements/thread: exclusive scan -> rowptr, cursor
__global__ void k_scan() {
    __shared__ int warpsum[32];
    int tid = threadIdx.x, lane = tid & 31, wid = tid >> 5;
    int carry = 0;
    if (tid == 0) g_rowptr[0] = 0;
    for (int base = 0; base < N_NODES; base += 4096) {
        int i0 = base + tid * 4;
        int4 v = make_int4(0, 0, 0, 0);
        if (i0 + 3 < N_NODES) {
            v = *(const int4*)&g_deg[i0];
        } else {
            if (i0 + 0 < N_NODES) v.x = g_deg[i0 + 0];
            if (i0 + 1 < N_NODES) v.y = g_deg[i0 + 1];
            if (i0 + 2 < N_NODES) v.z = g_deg[i0 + 2];
            if (i0 + 3 < N_NODES) v.w = g_deg[i0 + 3];
        }
        int s = v.x + v.y + v.z + v.w;
        int x = s;
        #pragma unroll
        for (int off = 1; off < 32; off <<= 1) {
            int t = __shfl_up_sync(0xffffffffu, x, off);
            if (lane >= off) x += t;
        }
        if (lane == 31) warpsum[wid] = x;
        __syncthreads();
        if (wid == 0) {
            int w = warpsum[lane];
            #pragma unroll
            for (int off = 1; off < 32; off <<= 1) {
                int t = __shfl_up_sync(0xffffffffu, w, off);
                if (lane >= off) w += t;
            }
            warpsum[lane] = w;
        }
        __syncthreads();
        int woff = (wid > 0) ? warpsum[wid - 1] : 0;
        int excl = carry + woff + (x - s);
        int p0 = excl + v.x, p1 = p0 + v.y, p2 = p1 + v.z, p3 = p2 + v.w;
        if (i0 + 0 < N_NODES) { g_cursor[i0 + 0] = excl; g_rowptr[i0 + 1] = p0; }
        if (i0 + 1 < N_NODES) { g_cursor[i0 + 1] = p0;   g_rowptr[i0 + 2] = p1; }
        if (i0 + 2 < N_NODES) { g_cursor[i0 + 2] = p1;   g_rowptr[i0 + 3] = p2; }
        if (i0 + 3 < N_NODES) { g_cursor[i0 + 3] = p2;   g_rowptr[i0 + 4] = p3; }
        carry += warpsum[31];
        __syncthreads();
    }
}

__global__ void k_scatter(const int* __restrict__ ei) {
    int e = blockIdx.x * blockDim.x + threadIdx.x;
    if (e >= N_EDGES) return;
    int d = ei[N_EDGES + e];
    int s = ei[e];
    int p = atomicAdd(&g_cursor[d], 1);
    g_csrsrc[p] = s;
}

// ---------------- TF32 tensor-core GEMM, fp16 activations ----------------
// out[N,64] = A[N, K] @ W[K, 64],  K = KCH*16
// IN_SEL: 0 = Aext fp32, 1 = g_h fp16, 2 = g_a fp16.  OUT_SEL: 0 = g_y, 1 = g_h.
template <int KCH, bool RELU, bool POOL, int IN_SEL, int OUT_SEL>
__global__ __launch_bounds__(256) void k_gemm_tc(const float* __restrict__ Aext,
                                                 const float* __restrict__ W,
                                                 const int* __restrict__ batch) {
    constexpr int K = KCH * 16;
    const __half* Ah = (IN_SEL == 1) ? (const __half*)g_h : (const __half*)g_a;
    __half* outb = (OUT_SEL == 0) ? g_y : g_h;

    __shared__ unsigned sA[256 * 17];  // 256 rows x 16 k, stride 17
    __shared__ unsigned sW[16 * 65];   // 16 k x 64 n, stride 65

    int tid = threadIdx.x;
    int wid = tid >> 5, lane = tid & 31;
    int tg = lane >> 2, tig = lane & 3;
    int row0 = blockIdx.x * 256;

    float c[2][8][4];
    #pragma unroll
    for (int mt = 0; mt < 2; mt++)
        #pragma unroll
        for (int nt = 0; nt < 8; nt++)
            #pragma unroll
            for (int j = 0; j < 4; j++) c[mt][nt][j] = 0.f;

    for (int ch = 0; ch < KCH; ch++) {
        int kbase = ch * 16;
        if (IN_SEL == 0) {
            // fp32 input: 256 rows x 16 k = 1024 float4
            #pragma unroll
            for (int i = 0; i < 4; i++) {
                int idx = tid + i * 256;
                int r = idx >> 2, c4 = idx & 3;
                int grow = row0 + r;
                float4 v = make_float4(0.f, 0.f, 0.f, 0.f);
                if (grow < N_NODES)
                    v = *(const float4*)(Aext + (size_t)grow * K + kbase + c4 * 4);
                unsigned* p = &sA[r * 17 + c4 * 4];
                p[0] = f2tf(v.x); p[1] = f2tf(v.y); p[2] = f2tf(v.z); p[3] = f2tf(v.w);
            }
        } else {
            // fp16 input: 256 rows x 16 k = 512 x (8 halves); 2 per thread
            #pragma unroll
            for (int i = 0; i < 2; i++) {
                int idx = tid + i * 256;
                int r = idx >> 1, h8 = (idx & 1) * 8;
                int grow = row0 + r;
                uint4 raw = make_uint4(0u, 0u, 0u, 0u);
                if (grow < N_NODES)
                    raw = *(const uint4*)(Ah + (size_t)grow * K + kbase + h8);
                unsigned* p = &sA[r * 17 + h8];
                float2 f;
                f = __half22float2(*(__half2*)&raw.x); p[0] = f2tf(f.x); p[1] = f2tf(f.y);
                f = __half22float2(*(__half2*)&raw.y); p[2] = f2tf(f.x); p[3] = f2tf(f.y);
                f = __half22float2(*(__half2*)&raw.z); p[4] = f2tf(f.x); p[5] = f2tf(f.y);
                f = __half22float2(*(__half2*)&raw.w); p[6] = f2tf(f.x); p[7] = f2tf(f.y);
            }
        }
        // load W chunk: 16 k x 64 n (fp32 global)
        {
            int k = tid >> 4, c4 = tid & 15;
            float4 v = *(const float4*)(W + (size_t)(kbase + k) * 64 + c4 * 4);
            unsigned* p = &sW[k * 65 + c4 * 4];
            p[0] = f2tf(v.x); p[1] = f2tf(v.y); p[2] = f2tf(v.z); p[3] = f2tf(v.w);
        }
        __syncthreads();

        #pragma unroll
        for (int ks = 0; ks < 2; ks++) {
            int ko = ks * 8;
            unsigned a[2][4];
            #pragma unroll
            for (int mt = 0; mt < 2; mt++) {
                int rr = wid * 32 + mt * 16 + tg;
                a[mt][0] = sA[rr * 17 + ko + tig];
                a[mt][1] = sA[(rr + 8) * 17 + ko + tig];
                a[mt][2] = sA[rr * 17 + ko + tig + 4];
                a[mt][3] = sA[(rr + 8) * 17 + ko + tig + 4];
            }
            #pragma unroll
            for (int nt = 0; nt < 8; nt++) {
                unsigned b0 = sW[(ko + tig) * 65 + nt * 8 + tg];
                unsigned b1 = sW[(ko + tig + 4) * 65 + nt * 8 + tg];
                mma_tf32(c[0][nt], a[0], b0, b1);
                mma_tf32(c[1][nt], a[1], b0, b1);
            }
        }
        __syncthreads();
    }

    // epilogue
    #pragma unroll
    for (int mt = 0; mt < 2; mt++) {
        int row = row0 + wid * 32 + mt * 16 + tg;
        #pragma unroll
        for (int half_i = 0; half_i < 2; half_i++) {
            int r = row + half_i * 8;
            if (r < N_NODES) {
                int b = POOL ? batch[r] : 0;
                #pragma unroll
                for (int nt = 0; nt < 8; nt++) {
                    int col = nt * 8 + tig * 2;
                    float v0 = c[mt][nt][half_i * 2 + 0];
                    float v1 = c[mt][nt][half_i * 2 + 1];
                    if (RELU) { v0 = fmaxf(v0, 0.f); v1 = fmaxf(v1, 0.f); }
                    if (POOL) {
                        atomicAdd(&g_pool[b * HD + col], v0);
                        atomicAdd(&g_pool[b * HD + col + 1], v1);
                    } else {
                        *(__half2*)(outb + (size_t)r * HD + col) =
                            __float22half2_rn(make_float2(v0, v1));
                    }
                }
            }
        }
    }
}

// ---------------- aggregation + BN + relu (fp16 in/out, fp32 accumulate) ----------
// g_a[i] = relu(BN(g_y[i] + sum_{e:dst=i} g_y[src[e]]))
__global__ __launch_bounds__(256) void k_agg(const float* __restrict__ gam,
                                             const float* __restrict__ bet,
                                             const float* __restrict__ mea,
                                             const float* __restrict__ var) {
    int gwarp = (blockIdx.x * 256 + threadIdx.x) >> 5;  // one warp per node
    int lane = threadIdx.x & 31;
    if (gwarp >= N_NODES) return;
    const __half2* yv = (const __half2*)g_y;
    float2 acc = __half22float2(yv[(size_t)gwarp * 32 + lane]);
    int beg = g_rowptr[gwarp], end = g_rowptr[gwarp + 1];
    for (int base = beg; base < end; base += 32) {
        int n = end - base;
        if (n > 32) n = 32;
        int idx = (lane < n) ? g_csrsrc[base + lane] : 0;
        int t = 0;
        for (; t + 4 <= n; t += 4) {
            int s0 = __shfl_sync(0xffffffffu, idx, t + 0);
            int s1 = __shfl_sync(0xffffffffu, idx, t + 1);
            int s2 = __shfl_sync(0xffffffffu, idx, t + 2);
            int s3 = __shfl_sync(0xffffffffu, idx, t + 3);
            float2 v0 = __half22float2(yv[(size_t)s0 * 32 + lane]);
            float2 v1 = __half22float2(yv[(size_t)s1 * 32 + lane]);
            float2 v2 = __half22float2(yv[(size_t)s2 * 32 + lane]);
            float2 v3 = __half22float2(yv[(size_t)s3 * 32 + lane]);
            acc.x += (v0.x + v1.x) + (v2.x + v3.x);
            acc.y += (v0.y + v1.y) + (v2.y + v3.y);
        }
        for (; t < n; t++) {
            int s = __shfl_sync(0xffffffffu, idx, t);
            float2 v = __half22float2(yv[(size_t)s * 32 + lane]);
            acc.x += v.x;
            acc.y += v.y;
        }
    }
    int c0 = lane * 2;
    float i0 = rsqrtf(var[c0] + BN_EPS) * gam[c0];
    float i1 = rsqrtf(var[c0 + 1] + BN_EPS) * gam[c0 + 1];
    float h0 = fmaxf((acc.x - mea[c0]) * i0 + bet[c0], 0.f);
    float h1 = fmaxf((acc.y - mea[c0 + 1]) * i1 + bet[c0 + 1], 0.f);
    ((__half2*)g_a)[(size_t)gwarp * 32 + lane] = __float22half2_rn(make_float2(h0, h1));
}

// ---------------- final head: mean, lin1+relu, lin2+bias, log_softmax ----------------
__global__ void k_final(const float* __restrict__ lin1, const float* __restrict__ lin2,
                        const float* __restrict__ lb, float* __restrict__ out) {
    __shared__ float sL1[64 * 64];
    __shared__ float sL2[64 * 10];
    __shared__ float sB[10];
    int tid = threadIdx.x;
    for (int i = tid; i < 64 * 64; i += 128) sL1[i] = lin1[i];
    for (int i = tid; i < 64 * 10; i += 128) sL2[i] = lin2[i];
    if (tid < 10) sB[tid] = lb[tid];
    __syncthreads();
    if (tid < N_GRAPHS) {
        float cnt = (float)g_cnt[tid];
        if (cnt < 1.f) cnt = 1.f;
        float pooled[64];
        #pragma unroll
        for (int k = 0; k < 64; k++) pooled[k] = g_pool[tid * 64 + k] / cnt;
        float o[10];
        #pragma unroll
        for (int c = 0; c < 10; c++) o[c] = sB[c];
        for (int j = 0; j < 64; j++) {
            float z = 0.f;
            #pragma unroll
            for (int k = 0; k < 64; k++) z += pooled[k] * sL1[k * 64 + j];
            z = fmaxf(z, 0.f);
            #pragma unroll
            for (int c = 0; c < 10; c++) o[c] += z * sL2[j * 10 + c];
        }
        float mx = o[0];
        #pragma unroll
        for (int c = 1; c < 10; c++) mx = fmaxf(mx, o[c]);
        float se = 0.f;
        #pragma unroll
        for (int c = 0; c < 10; c++) se += expf(o[c] - mx);
        float lse = logf(se) + mx;
        #pragma unroll
        for (int c = 0; c < 10; c++) out[tid * 10 + c] = o[c] - lse;
    }
}

// ---------------- launch (kernel launches ONLY) ----------------
extern "C" void kernel_launch(void* const* d_in, const int* in_sizes, int n_in,
                              void* d_out, int out_size) {
    const float* x      = (const float*)d_in[0];
    const int*   ei     = (const int*)d_in[1];
    const int*   batch  = (const int*)d_in[2];
    const float* W1_0   = (const float*)d_in[3];
    const float* bn_g_0 = (const float*)d_in[4];
    const float* bn_b_0 = (const float*)d_in[5];
    const float* bn_m_0 = (const float*)d_in[6];
    const float* bn_v_0 = (const float*)d_in[7];
    const float* W2_0   = (const float*)d_in[8];
    const float* W1_r   = (const float*)d_in[9];
    const float* bn_g_r = (const float*)d_in[10];
    const float* bn_b_r = (const float*)d_in[11];
    const float* bn_m_r = (const float*)d_in[12];
    const float* bn_v_r = (const float*)d_in[13];
    const float* W2_r   = (const float*)d_in[14];
    const float* lin1   = (const float*)d_in[15];
    const float* lin2   = (const float*)d_in[16];
    const float* lin2b  = (const float*)d_in[17];
    float* out = (float*)d_out;

    const int TPB = 256;
    int gridNodes = (N_NODES + TPB - 1) / TPB;
    int gridEdges = (N_EDGES + TPB - 1) / TPB;
    int gridGemm = (N_NODES + 255) / 256;           // 391
    int gridAgg = (N_NODES * 32 + TPB - 1) / TPB;   // warp per node

    // CSR build
    k_init<<<gridNodes, TPB>>>();
    k_count<<<gridEdges, TPB>>>(ei, batch);
    k_scan<<<1, 1024>>>();
    k_scatter<<<gridEdges, TPB>>>(ei);

    // layer 0: y = x@W1_0 (K=128 fp32 input)
    k_gemm_tc<8, false, false, 0, 0><<<gridGemm, TPB>>>(x, W1_0, nullptr);
    k_agg<<<gridAgg, TPB>>>(bn_g_0, bn_b_0, bn_m_0, bn_v_0);
    k_gemm_tc<4, true, false, 2, 1><<<gridGemm, TPB>>>(nullptr, W2_0, nullptr);

    // layers 1..2
    for (int l = 0; l < 2; l++) {
        k_gemm_tc<4, false, false, 1, 0><<<gridGemm, TPB>>>(nullptr, W1_r + (size_t)l * 4096, nullptr);
        k_agg<<<gridAgg, TPB>>>(bn_g_r + l * 64, bn_b_r + l * 64,
                                bn_m_r + l * 64, bn_v_r + l * 64);
        k_gemm_tc<4, true, false, 2, 1><<<gridGemm, TPB>>>(nullptr, W2_r + (size_t)l * 4096, nullptr);
    }

    // layer 3: last GEMM fuses relu + mean-pool accumulation
    k_gemm_tc<4, false, false, 1, 0><<<gridGemm, TPB>>>(nullptr, W1_r + (size_t)2 * 4096, nullptr);
    k_agg<<<gridAgg, TPB>>>(bn_g_r + 2 * 64, bn_b_r + 2 * 64,
                            bn_m_r + 2 * 64, bn_v_r + 2 * 64);
    k_gemm_tc<4, true, true, 2, 1><<<gridGemm, TPB>>>(nullptr, W2_r + (size_t)2 * 4096, batch);

    // head
    k_final<<<1, 128>>>(lin1, lin2, lin2b, out);
}

// round 7
// speedup vs baseline: 1.5412x; 1.1672x over previous
#include <cuda_runtime.h>
#include <cuda_fp16.h>
#include <math.h>

#define N_NODES 100000
#define N_EDGES 1000000
#define N_GRAPHS 128
#define HD 64
#define BN_EPS 1e-5f

#define SCAN_BLK 25            // ceil(100000 / 4096)

// ---------------- scratch (device globals; no allocation allowed) ----------------
__device__ __align__(16) int    g_rowptr[N_NODES + 1];
__device__ __align__(16) int    g_cursor[N_NODES];
__device__ __align__(16) int    g_deg[N_NODES];
__device__ __align__(16) int    g_bsum[SCAN_BLK];
__device__ __align__(16) int    g_boff[SCAN_BLK];
__device__ __align__(16) int    g_csrsrc[N_EDGES];
__device__ __align__(16) __half g_h[N_NODES * HD];
__device__ __align__(16) __half g_y[N_NODES * HD];
__device__ __align__(16) __half g_a[N_NODES * HD];
__device__ __align__(16) float  g_pool[N_GRAPHS * HD];
__device__ __align__(16) int    g_cnt[N_GRAPHS];

// ---------------- helpers ----------------
__device__ __forceinline__ unsigned f2tf(float f) {
    unsigned u;
    asm("cvt.rna.tf32.f32 %0, %1;" : "=r"(u) : "f"(f));
    return u;
}
__device__ __forceinline__ void mma_tf32(float* c, const unsigned* a,
                                         unsigned b0, unsigned b1) {
    asm("mma.sync.aligned.m16n8k8.row.col.f32.tf32.tf32.f32 "
        "{%0,%1,%2,%3},{%4,%5,%6,%7},{%8,%9},{%0,%1,%2,%3};"
        : "+f"(c[0]), "+f"(c[1]), "+f"(c[2]), "+f"(c[3])
        : "r"(a[0]), "r"(a[1]), "r"(a[2]), "r"(a[3]), "r"(b0), "r"(b1));
}

// ---------------- CSR build ----------------
__global__ void k_init() {
    int i = blockIdx.x * blockDim.x + threadIdx.x;
    if (i < N_NODES) g_deg[i] = 0;
    if (i < N_GRAPHS * HD) g_pool[i] = 0.f;
    if (i < N_GRAPHS) g_cnt[i] = 0;
}

__global__ void k_count(const int* __restrict__ ei,
                        const int* __restrict__ batch) {
    int e = blockIdx.x * blockDim.x + threadIdx.x;
    if (e < N_EDGES) atomicAdd(&g_deg[ei[N_EDGES + e]], 1);
    if (e < N_NODES) atomicAdd(&g_cnt[batch[e]], 1);
}

// ---- parallel scan, phase 1: block-local exclusive scan (4096 elems/block) ----
__global__ __launch_bounds__(1024) void k_scan1() {
    __shared__ int warpsum[32];
    int tid = threadIdx.x, lane = tid & 31, wid = tid >> 5;
    int i0 = blockIdx.x * 4096 + tid * 4;
    int4 v = make_int4(0, 0, 0, 0);
    if (i0 + 3 < N_NODES) {
        v = *(const int4*)&g_deg[i0];
    } else {
        if (i0 + 0 < N_NODES) v.x = g_deg[i0 + 0];
        if (i0 + 1 < N_NODES) v.y = g_deg[i0 + 1];
        if (i0 + 2 < N_NODES) v.z = g_deg[i0 + 2];
        if (i0 + 3 < N_NODES) v.w = g_deg[i0 + 3];
    }
    int s = v.x + v.y + v.z + v.w;
    int x = s;
    #pragma unroll
    for (int off = 1; off < 32; off <<= 1) {
        int t = __shfl_up_sync(0xffffffffu, x, off);
        if (lane >= off) x += t;
    }
    if (lane == 31) warpsum[wid] = x;
    __syncthreads();
    if (wid == 0) {
        int w = warpsum[lane];
        #pragma unroll
        for (int off = 1; off < 32; off <<= 1) {
            int t = __shfl_up_sync(0xffffffffu, w, off);
            if (lane >= off) w += t;
        }
        warpsum[lane] = w;
    }
    __syncthreads();
    int woff = (wid > 0) ? warpsum[wid - 1] : 0;
    int excl = woff + (x - s);  // exclusive within block
    int p0 = excl + v.x, p1 = p0 + v.y, p2 = p1 + v.z;
    if (i0 + 0 < N_NODES) g_cursor[i0 + 0] = excl;
    if (i0 + 1 < N_NODES) g_cursor[i0 + 1] = p0;
    if (i0 + 2 < N_NODES) g_cursor[i0 + 2] = p1;
    if (i0 + 3 < N_NODES) g_cursor[i0 + 3] = p2;
    if (tid == 1023) g_bsum[blockIdx.x] = warpsum[31];
}

// ---- phase 2: exclusive scan of 25 block sums (one warp) ----
__global__ void k_scan2() {
    int lane = threadIdx.x;
    int v = (lane < SCAN_BLK) ? g_bsum[lane] : 0;
    int x = v;
    #pragma unroll
    for (int off = 1; off < 32; off <<= 1) {
        int t = __shfl_up_sync(0xffffffffu, x, off);
        if (lane >= off) x += t;
    }
    if (lane < SCAN_BLK) g_boff[lane] = x - v;
}

// ---- phase 3: add block offsets; emit cursor (mutable) + rowptr (stable) ----
__global__ __launch_bounds__(1024) void k_scan3() {
    int off = g_boff[blockIdx.x];
    int i0 = blockIdx.x * 4096 + threadIdx.x * 4;
    if (i0 + 3 < N_NODES) {
        int4 c = *(const int4*)&g_cursor[i0];
        c.x += off; c.y += off; c.z += off; c.w += off;
        *(int4*)&g_cursor[i0] = c;
        *(int4*)&g_rowptr[i0] = c;
    } else {
        #pragma unroll
        for (int j = 0; j < 4; j++) {
            if (i0 + j < N_NODES) {
                int c = g_cursor[i0 + j] + off;
                g_cursor[i0 + j] = c;
                g_rowptr[i0 + j] = c;
            }
        }
    }
    if (blockIdx.x == 0 && threadIdx.x == 0) g_rowptr[N_NODES] = N_EDGES;
}

__global__ void k_scatter(const int* __restrict__ ei) {
    int e = blockIdx.x * blockDim.x + threadIdx.x;
    if (e >= N_EDGES) return;
    int d = ei[N_EDGES + e];
    int s = ei[e];
    int p = atomicAdd(&g_cursor[d], 1);
    g_csrsrc[p] = s;
}

// ---------------- TF32 tensor-core GEMM, fp16 activations ----------------
// out[N,64] = A[N, K] @ W[K, 64],  K = KCH*16
// IN_SEL: 0 = Aext fp32, 1 = g_h fp16, 2 = g_a fp16.  OUT_SEL: 0 = g_y, 1 = g_h.
template <int KCH, bool RELU, bool POOL, int IN_SEL, int OUT_SEL>
__global__ __launch_bounds__(256) void k_gemm_tc(const float* __restrict__ Aext,
                                                 const float* __restrict__ W,
                                                 const int* __restrict__ batch) {
    constexpr int K = KCH * 16;
    const __half* Ah = (IN_SEL == 1) ? (const __half*)g_h : (const __half*)g_a;
    __half* outb = (OUT_SEL == 0) ? g_y : g_h;

    __shared__ unsigned sA[256 * 17];  // 256 rows x 16 k, stride 17
    __shared__ unsigned sW[16 * 65];   // 16 k x 64 n, stride 65

    int tid = threadIdx.x;
    int wid = tid >> 5, lane = tid & 31;
    int tg = lane >> 2, tig = lane & 3;
    int row0 = blockIdx.x * 256;

    float c[2][8][4];
    #pragma unroll
    for (int mt = 0; mt < 2; mt++)
        #pragma unroll
        for (int nt = 0; nt < 8; nt++)
            #pragma unroll
            for (int j = 0; j < 4; j++) c[mt][nt][j] = 0.f;

    for (int ch = 0; ch < KCH; ch++) {
        int kbase = ch * 16;
        if (IN_SEL == 0) {
            #pragma unroll
            for (int i = 0; i < 4; i++) {
                int idx = tid + i * 256;
                int r = idx >> 2, c4 = idx & 3;
                int grow = row0 + r;
                float4 v = make_float4(0.f, 0.f, 0.f, 0.f);
                if (grow < N_NODES)
                    v = *(const float4*)(Aext + (size_t)grow * K + kbase + c4 * 4);
                unsigned* p = &sA[r * 17 + c4 * 4];
                p[0] = f2tf(v.x); p[1] = f2tf(v.y); p[2] = f2tf(v.z); p[3] = f2tf(v.w);
            }
        } else {
            #pragma unroll
            for (int i = 0; i < 2; i++) {
                int idx = tid + i * 256;
                int r = idx >> 1, h8 = (idx & 1) * 8;
                int grow = row0 + r;
                uint4 raw = make_uint4(0u, 0u, 0u, 0u);
                if (grow < N_NODES)
                    raw = *(const uint4*)(Ah + (size_t)grow * K + kbase + h8);
                unsigned* p = &sA[r * 17 + h8];
                float2 f;
                f = __half22float2(*(__half2*)&raw.x); p[0] = f2tf(f.x); p[1] = f2tf(f.y);
                f = __half22float2(*(__half2*)&raw.y); p[2] = f2tf(f.x); p[3] = f2tf(f.y);
                f = __half22float2(*(__half2*)&raw.z); p[4] = f2tf(f.x); p[5] = f2tf(f.y);
                f = __half22float2(*(__half2*)&raw.w); p[6] = f2tf(f.x); p[7] = f2tf(f.y);
            }
        }
        {
            int k = tid >> 4, c4 = tid & 15;
            float4 v = *(const float4*)(W + (size_t)(kbase + k) * 64 + c4 * 4);
            unsigned* p = &sW[k * 65 + c4 * 4];
            p[0] = f2tf(v.x); p[1] = f2tf(v.y); p[2] = f2tf(v.z); p[3] = f2tf(v.w);
        }
        __syncthreads();

        #pragma unroll
        for (int ks = 0; ks < 2; ks++) {
            int ko = ks * 8;
            unsigned a[2][4];
            #pragma unroll
            for (int mt = 0; mt < 2; mt++) {
                int rr = wid * 32 + mt * 16 + tg;
                a[mt][0] = sA[rr * 17 + ko + tig];
                a[mt][1] = sA[(rr + 8) * 17 + ko + tig];
                a[mt][2] = sA[rr * 17 + ko + tig + 4];
                a[mt][3] = sA[(rr + 8) * 17 + ko + tig + 4];
            }
            #pragma unroll
            for (int nt = 0; nt < 8; nt++) {
                unsigned b0 = sW[(ko + tig) * 65 + nt * 8 + tg];
                unsigned b1 = sW[(ko + tig + 4) * 65 + nt * 8 + tg];
                mma_tf32(c[0][nt], a[0], b0, b1);
                mma_tf32(c[1][nt], a[1], b0, b1);
            }
        }
        __syncthreads();
    }

    #pragma unroll
    for (int mt = 0; mt < 2; mt++) {
        int row = row0 + wid * 32 + mt * 16 + tg;
        #pragma unroll
        for (int half_i = 0; half_i < 2; half_i++) {
            int r = row + half_i * 8;
            if (r < N_NODES) {
                int b = POOL ? batch[r] : 0;
                #pragma unroll
                for (int nt = 0; nt < 8; nt++) {
                    int col = nt * 8 + tig * 2;
                    float v0 = c[mt][nt][half_i * 2 + 0];
                    float v1 = c[mt][nt][half_i * 2 + 1];
                    if (RELU) { v0 = fmaxf(v0, 0.f); v1 = fmaxf(v1, 0.f); }
                    if (POOL) {
                        atomicAdd(&g_pool[b * HD + col], v0);
                        atomicAdd(&g_pool[b * HD + col + 1], v1);
                    } else {
                        *(__half2*)(outb + (size_t)r * HD + col) =
                            __float22half2_rn(make_float2(v0, v1));
                    }
                }
            }
        }
    }
}

// ---------------- aggregation + BN + relu (fp16 in/out, fp32 accumulate) ----------
__global__ __launch_bounds__(256) void k_agg(const float* __restrict__ gam,
                                             const float* __restrict__ bet,
                                             const float* __restrict__ mea,
                                             const float* __restrict__ var) {
    int gwarp = (blockIdx.x * 256 + threadIdx.x) >> 5;  // one warp per node
    int lane = threadIdx.x & 31;
    if (gwarp >= N_NODES) return;
    const __half2* yv = (const __half2*)g_y;
    float2 acc = __half22float2(yv[(size_t)gwarp * 32 + lane]);
    int beg = g_rowptr[gwarp], end = g_rowptr[gwarp + 1];
    for (int base = beg; base < end; base += 32) {
        int n = end - base;
        if (n > 32) n = 32;
        int idx = (lane < n) ? g_csrsrc[base + lane] : 0;
        int t = 0;
        for (; t + 4 <= n; t += 4) {
            int s0 = __shfl_sync(0xffffffffu, idx, t + 0);
            int s1 = __shfl_sync(0xffffffffu, idx, t + 1);
            int s2 = __shfl_sync(0xffffffffu, idx, t + 2);
            int s3 = __shfl_sync(0xffffffffu, idx, t + 3);
            float2 v0 = __half22float2(yv[(size_t)s0 * 32 + lane]);
            float2 v1 = __half22float2(yv[(size_t)s1 * 32 + lane]);
            float2 v2 = __half22float2(yv[(size_t)s2 * 32 + lane]);
            float2 v3 = __half22float2(yv[(size_t)s3 * 32 + lane]);
            acc.x += (v0.x + v1.x) + (v2.x + v3.x);
            acc.y += (v0.y + v1.y) + (v2.y + v3.y);
        }
        for (; t < n; t++) {
            int s = __shfl_sync(0xffffffffu, idx, t);
            float2 v = __half22float2(yv[(size_t)s * 32 + lane]);
            acc.x += v.x;
            acc.y += v.y;
        }
    }
    int c0 = lane * 2;
    float i0 = rsqrtf(var[c0] + BN_EPS) * gam[c0];
    float i1 = rsqrtf(var[c0 + 1] + BN_EPS) * gam[c0 + 1];
    float h0 = fmaxf((acc.x - mea[c0]) * i0 + bet[c0], 0.f);
    float h1 = fmaxf((acc.y - mea[c0 + 1]) * i1 + bet[c0 + 1], 0.f);
    ((__half2*)g_a)[(size_t)gwarp * 32 + lane] = __float22half2_rn(make_float2(h0, h1));
}

// ---------------- final head ----------------
__global__ void k_final(const float* __restrict__ lin1, const float* __restrict__ lin2,
                        const float* __restrict__ lb, float* __restrict__ out) {
    __shared__ float sL1[64 * 64];
    __shared__ float sL2[64 * 10];
    __shared__ float sB[10];
    int tid = threadIdx.x;
    for (int i = tid; i < 64 * 64; i += 128) sL1[i] = lin1[i];
    for (int i = tid; i < 64 * 10; i += 128) sL2[i] = lin2[i];
    if (tid < 10) sB[tid] = lb[tid];
    __syncthreads();
    if (tid < N_GRAPHS) {
        float cnt = (float)g_cnt[tid];
        if (cnt < 1.f) cnt = 1.f;
        float pooled[64];
        #pragma unroll
        for (int k = 0; k < 64; k++) pooled[k] = g_pool[tid * 64 + k] / cnt;
        float o[10];
        #pragma unroll
        for (int c = 0; c < 10; c++) o[c] = sB[c];
        for (int j = 0; j < 64; j++) {
            float z = 0.f;
            #pragma unroll
            for (int k = 0; k < 64; k++) z += pooled[k] * sL1[k * 64 + j];
            z = fmaxf(z, 0.f);
            #pragma unroll
            for (int c = 0; c < 10; c++) o[c] += z * sL2[j * 10 + c];
        }
        float mx = o[0];
        #pragma unroll
        for (int c = 1; c < 10; c++) mx = fmaxf(mx, o[c]);
        float se = 0.f;
        #pragma unroll
        for (int c = 0; c < 10; c++) se += expf(o[c] - mx);
        float lse = logf(se) + mx;
        #pragma unroll
        for (int c = 0; c < 10; c++) out[tid * 10 + c] = o[c] - lse;
    }
}

// ---------------- launch (kernel launches ONLY) ----------------
extern "C" void kernel_launch(void* const* d_in, const int* in_sizes, int n_in,
                              void* d_out, int out_size) {
    const float* x      = (const float*)d_in[0];
    const int*   ei     = (const int*)d_in[1];
    const int*   batch  = (const int*)d_in[2];
    const float* W1_0   = (const float*)d_in[3];
    const float* bn_g_0 = (const float*)d_in[4];
    const float* bn_b_0 = (const float*)d_in[5];
    const float* bn_m_0 = (const float*)d_in[6];
    const float* bn_v_0 = (const float*)d_in[7];
    const float* W2_0   = (const float*)d_in[8];
    const float* W1_r   = (const float*)d_in[9];
    const float* bn_g_r = (const float*)d_in[10];
    const float* bn_b_r = (const float*)d_in[11];
    const float* bn_m_r = (const float*)d_in[12];
    const float* bn_v_r = (const float*)d_in[13];
    const float* W2_r   = (const float*)d_in[14];
    const float* lin1   = (const float*)d_in[15];
    const float* lin2   = (const float*)d_in[16];
    const float* lin2b  = (const float*)d_in[17];
    float* out = (float*)d_out;

    const int TPB = 256;
    int gridNodes = (N_NODES + TPB - 1) / TPB;
    int gridEdges = (N_EDGES + TPB - 1) / TPB;
    int gridGemm = (N_NODES + 255) / 256;           // 391
    int gridAgg = (N_NODES * 32 + TPB - 1) / TPB;   // warp per node

    // CSR build (parallel scan)
    k_init<<<gridNodes, TPB>>>();
    k_count<<<gridEdges, TPB>>>(ei, batch);
    k_scan1<<<SCAN_BLK, 1024>>>();
    k_scan2<<<1, 32>>>();
    k_scan3<<<SCAN_BLK, 1024>>>();
    k_scatter<<<gridEdges, TPB>>>(ei);

    // layer 0
    k_gemm_tc<8, false, false, 0, 0><<<gridGemm, TPB>>>(x, W1_0, nullptr);
    k_agg<<<gridAgg, TPB>>>(bn_g_0, bn_b_0, bn_m_0, bn_v_0);
    k_gemm_tc<4, true, false, 2, 1><<<gridGemm, TPB>>>(nullptr, W2_0, nullptr);

    // layers 1..2
    for (int l = 0; l < 2; l++) {
        k_gemm_tc<4, false, false, 1, 0><<<gridGemm, TPB>>>(nullptr, W1_r + (size_t)l * 4096, nullptr);
        k_agg<<<gridAgg, TPB>>>(bn_g_r + l * 64, bn_b_r + l * 64,
                                bn_m_r + l * 64, bn_v_r + l * 64);
        k_gemm_tc<4, true, false, 2, 1><<<gridGemm, TPB>>>(nullptr, W2_r + (size_t)l * 4096, nullptr);
    }

    // layer 3: last GEMM fuses relu + mean-pool accumulation
    k_gemm_tc<4, false, false, 1, 0><<<gridGemm, TPB>>>(nullptr, W1_r + (size_t)2 * 4096, nullptr);
    k_agg<<<gridAgg, TPB>>>(bn_g_r + 2 * 64, bn_b_r + 2 * 64,
                            bn_m_r + 2 * 64, bn_v_r + 2 * 64);
    k_gemm_tc<4, true, true, 2, 1><<<gridGemm, TPB>>>(nullptr, W2_r + (size_t)2 * 4096, batch);

    // head
    k_final<<<1, 128>>>(lin1, lin2, lin2b, out);
}

// round 8
// speedup vs baseline: 1.8102x; 1.1746x over previous
#include <cuda_runtime.h>
#include <cuda_fp16.h>
#include <math.h>

#define N_NODES 100000
#define N_EDGES 1000000
#define N_GRAPHS 128
#define HD 64
#define BN_EPS 1e-5f

#define SCAN_BLK 25            // ceil(100000 / 4096)

// ---------------- scratch (device globals; no allocation allowed) ----------------
__device__ __align__(16) int    g_rowptr[N_NODES + 1];
__device__ __align__(16) int    g_cursor[N_NODES];
__device__ __align__(16) int    g_deg[N_NODES];
__device__ __align__(16) int    g_bsum[SCAN_BLK];
__device__ __align__(16) int    g_csrsrc[N_EDGES];
__device__ __align__(16) __half g_y[N_NODES * HD];
__device__ __align__(16) __half g_a[N_NODES * HD];
__device__ __align__(16) float  g_pool[N_GRAPHS * HD];
__device__ __align__(16) int    g_cnt[N_GRAPHS];

// ---------------- helpers ----------------
__device__ __forceinline__ unsigned f2tf(float f) {
    unsigned u;
    asm("cvt.rna.tf32.f32 %0, %1;" : "=r"(u) : "f"(f));
    return u;
}
__device__ __forceinline__ void mma_tf32(float* c, const unsigned* a,
                                         unsigned b0, unsigned b1) {
    asm("mma.sync.aligned.m16n8k8.row.col.f32.tf32.tf32.f32 "
        "{%0,%1,%2,%3},{%4,%5,%6,%7},{%8,%9},{%0,%1,%2,%3};"
        : "+f"(c[0]), "+f"(c[1]), "+f"(c[2]), "+f"(c[3])
        : "r"(a[0]), "r"(a[1]), "r"(a[2]), "r"(a[3]), "r"(b0), "r"(b1));
}

// ---------------- CSR build ----------------
__global__ void k_init() {
    int i = blockIdx.x * blockDim.x + threadIdx.x;
    if (i < N_NODES) g_deg[i] = 0;
    if (i < N_GRAPHS * HD) g_pool[i] = 0.f;
    if (i < N_GRAPHS) g_cnt[i] = 0;
}

__global__ void k_count(const int* __restrict__ ei,
                        const int* __restrict__ batch) {
    int e = blockIdx.x * blockDim.x + threadIdx.x;
    if (e < N_EDGES) atomicAdd(&g_deg[ei[N_EDGES + e]], 1);
    if (e < N_NODES) atomicAdd(&g_cnt[batch[e]], 1);
}

// ---- scan phase 1: block-local exclusive scan (4096 elems/block) -> g_cursor, g_bsum
__global__ __launch_bounds__(1024) void k_scan1() {
    __shared__ int warpsum[32];
    int tid = threadIdx.x, lane = tid & 31, wid = tid >> 5;
    int i0 = blockIdx.x * 4096 + tid * 4;
    int4 v = make_int4(0, 0, 0, 0);
    if (i0 + 3 < N_NODES) {
        v = *(const int4*)&g_deg[i0];
    } else {
        if (i0 + 0 < N_NODES) v.x = g_deg[i0 + 0];
        if (i0 + 1 < N_NODES) v.y = g_deg[i0 + 1];
        if (i0 + 2 < N_NODES) v.z = g_deg[i0 + 2];
        if (i0 + 3 < N_NODES) v.w = g_deg[i0 + 3];
    }
    int s = v.x + v.y + v.z + v.w;
    int x = s;
    #pragma unroll
    for (int off = 1; off < 32; off <<= 1) {
        int t = __shfl_up_sync(0xffffffffu, x, off);
        if (lane >= off) x += t;
    }
    if (lane == 31) warpsum[wid] = x;
    __syncthreads();
    if (wid == 0) {
        int w = warpsum[lane];
        #pragma unroll
        for (int off = 1; off < 32; off <<= 1) {
            int t = __shfl_up_sync(0xffffffffu, w, off);
            if (lane >= off) w += t;
        }
        warpsum[lane] = w;
    }
    __syncthreads();
    int woff = (wid > 0) ? warpsum[wid - 1] : 0;
    int excl = woff + (x - s);  // exclusive within block
    int p0 = excl + v.x, p1 = p0 + v.y, p2 = p1 + v.z;
    if (i0 + 0 < N_NODES) g_cursor[i0 + 0] = excl;
    if (i0 + 1 < N_NODES) g_cursor[i0 + 1] = p0;
    if (i0 + 2 < N_NODES) g_cursor[i0 + 2] = p1;
    if (i0 + 3 < N_NODES) g_cursor[i0 + 3] = p2;
    if (tid == 1023) g_bsum[blockIdx.x] = warpsum[31];
}

// ---- scan phase 2+3 merged: each block scans the 25 block sums itself, then
//      adds its offset; emits cursor (mutable) + rowptr (stable) ----
__global__ __launch_bounds__(1024) void k_scan23() {
    __shared__ int s_off;
    int tid = threadIdx.x;
    if (tid < 32) {
        int lane = tid;
        int v = (lane < SCAN_BLK) ? g_bsum[lane] : 0;
        int x = v;
        #pragma unroll
        for (int off = 1; off < 32; off <<= 1) {
            int t = __shfl_up_sync(0xffffffffu, x, off);
            if (lane >= off) x += t;
        }
        if (lane == blockIdx.x) s_off = x - v;
    }
    __syncthreads();
    int off = s_off;
    int i0 = blockIdx.x * 4096 + tid * 4;
    if (i0 + 3 < N_NODES) {
        int4 c = *(const int4*)&g_cursor[i0];
        c.x += off; c.y += off; c.z += off; c.w += off;
        *(int4*)&g_cursor[i0] = c;
        *(int4*)&g_rowptr[i0] = c;
    } else {
        #pragma unroll
        for (int j = 0; j < 4; j++) {
            if (i0 + j < N_NODES) {
                int c = g_cursor[i0 + j] + off;
                g_cursor[i0 + j] = c;
                g_rowptr[i0 + j] = c;
            }
        }
    }
    if (blockIdx.x == 0 && tid == 0) g_rowptr[N_NODES] = N_EDGES;
}

__global__ void k_scatter(const int* __restrict__ ei) {
    int e = blockIdx.x * blockDim.x + threadIdx.x;
    if (e >= N_EDGES) return;
    int d = ei[N_EDGES + e];
    int s = ei[e];
    int p = atomicAdd(&g_cursor[d], 1);
    g_csrsrc[p] = s;
}

// ---------------- layer-0 input GEMM: g_y = x[N,128] @ W1_0[128,64] (TF32) ----
__global__ __launch_bounds__(256) void k_gemm0(const float* __restrict__ A,
                                               const float* __restrict__ W) {
    constexpr int K = 128;
    __shared__ unsigned sA[256 * 17];
    __shared__ unsigned sW[16 * 65];
    int tid = threadIdx.x;
    int wid = tid >> 5, lane = tid & 31;
    int tg = lane >> 2, tig = lane & 3;
    int row0 = blockIdx.x * 256;

    float c[2][8][4];
    #pragma unroll
    for (int mt = 0; mt < 2; mt++)
        #pragma unroll
        for (int nt = 0; nt < 8; nt++)
            #pragma unroll
            for (int j = 0; j < 4; j++) c[mt][nt][j] = 0.f;

    for (int ch = 0; ch < 8; ch++) {
        int kbase = ch * 16;
        #pragma unroll
        for (int i = 0; i < 4; i++) {
            int idx = tid + i * 256;
            int r = idx >> 2, c4 = idx & 3;
            int grow = row0 + r;
            float4 v = make_float4(0.f, 0.f, 0.f, 0.f);
            if (grow < N_NODES)
                v = *(const float4*)(A + (size_t)grow * K + kbase + c4 * 4);
            unsigned* p = &sA[r * 17 + c4 * 4];
            p[0] = f2tf(v.x); p[1] = f2tf(v.y); p[2] = f2tf(v.z); p[3] = f2tf(v.w);
        }
        {
            int k = tid >> 4, c4 = tid & 15;
            float4 v = *(const float4*)(W + (size_t)(kbase + k) * 64 + c4 * 4);
            unsigned* p = &sW[k * 65 + c4 * 4];
            p[0] = f2tf(v.x); p[1] = f2tf(v.y); p[2] = f2tf(v.z); p[3] = f2tf(v.w);
        }
        __syncthreads();
        #pragma unroll
        for (int ks = 0; ks < 2; ks++) {
            int ko = ks * 8;
            unsigned a[2][4];
            #pragma unroll
            for (int mt = 0; mt < 2; mt++) {
                int rr = wid * 32 + mt * 16 + tg;
                a[mt][0] = sA[rr * 17 + ko + tig];
                a[mt][1] = sA[(rr + 8) * 17 + ko + tig];
                a[mt][2] = sA[rr * 17 + ko + tig + 4];
                a[mt][3] = sA[(rr + 8) * 17 + ko + tig + 4];
            }
            #pragma unroll
            for (int nt = 0; nt < 8; nt++) {
                unsigned b0 = sW[(ko + tig) * 65 + nt * 8 + tg];
                unsigned b1 = sW[(ko + tig + 4) * 65 + nt * 8 + tg];
                mma_tf32(c[0][nt], a[0], b0, b1);
                mma_tf32(c[1][nt], a[1], b0, b1);
            }
        }
        __syncthreads();
    }
    #pragma unroll
    for (int mt = 0; mt < 2; mt++) {
        int row = row0 + wid * 32 + mt * 16 + tg;
        #pragma unroll
        for (int half_i = 0; half_i < 2; half_i++) {
            int r = row + half_i * 8;
            if (r < N_NODES) {
                #pragma unroll
                for (int nt = 0; nt < 8; nt++) {
                    int col = nt * 8 + tig * 2;
                    *(__half2*)(g_y + (size_t)r * HD + col) =
                        __float22half2_rn(make_float2(c[mt][nt][half_i * 2 + 0],
                                                      c[mt][nt][half_i * 2 + 1]));
                }
            }
        }
    }
}

// ---------------- chained dual GEMM ----------------
// Phase 1: h = relu(g_a[rows] @ W2)         (in smem, never hits global)
// DUAL:    y = h @ W1next -> g_y (fp16)
// !DUAL (POOL): atomicAdd h into g_pool (mean-pool accumulate)
// 128-row tile, 128 threads (4 warps), warp owns 32 rows x 64 cols.
template <bool DUAL>
__global__ __launch_bounds__(128) void k_dual(const float* __restrict__ W2,
                                              const float* __restrict__ W1n,
                                              const int* __restrict__ batch) {
    __shared__ unsigned sA[128 * 68];
    __shared__ unsigned sW[16 * 68];

    int tid = threadIdx.x, wid = tid >> 5, lane = tid & 31;
    int tg = lane >> 2, tig = lane & 3;
    int row0 = blockIdx.x * 128;

    // load A = g_a rows (fp16 -> tf32 in smem)
    #pragma unroll
    for (int i = 0; i < 8; i++) {
        int idx = tid + i * 128;           // 1024 uint4 total
        int r = idx >> 3, seg = idx & 7;   // 8 halves per uint4
        int grow = row0 + r;
        uint4 raw = make_uint4(0u, 0u, 0u, 0u);
        if (grow < N_NODES)
            raw = *(const uint4*)(g_a + (size_t)grow * HD + seg * 8);
        unsigned* p = &sA[r * 68 + seg * 8];
        float2 f;
        f = __half22float2(*(__half2*)&raw.x); p[0] = f2tf(f.x); p[1] = f2tf(f.y);
        f = __half22float2(*(__half2*)&raw.y); p[2] = f2tf(f.x); p[3] = f2tf(f.y);
        f = __half22float2(*(__half2*)&raw.z); p[4] = f2tf(f.x); p[5] = f2tf(f.y);
        f = __half22float2(*(__half2*)&raw.w); p[6] = f2tf(f.x); p[7] = f2tf(f.y);
    }

    float c[2][8][4];
    #pragma unroll
    for (int mt = 0; mt < 2; mt++)
        #pragma unroll
        for (int nt = 0; nt < 8; nt++)
            #pragma unroll
            for (int j = 0; j < 4; j++) c[mt][nt][j] = 0.f;

    // ---- GEMM1: A @ W2 ----
    for (int ch = 0; ch < 4; ch++) {
        __syncthreads();
        #pragma unroll
        for (int it = 0; it < 2; it++) {
            int id = tid + it * 128;
            int k = id >> 4, c4 = id & 15;
            float4 v = *(const float4*)(W2 + (size_t)(ch * 16 + k) * 64 + c4 * 4);
            unsigned* p = &sW[k * 68 + c4 * 4];
            p[0] = f2tf(v.x); p[1] = f2tf(v.y); p[2] = f2tf(v.z); p[3] = f2tf(v.w);
        }
        __syncthreads();
        #pragma unroll
        for (int ks = 0; ks < 2; ks++) {
            int ko = ks * 8;
            int kg = ch * 16 + ko;
            unsigned a[2][4];
            #pragma unroll
            for (int mt = 0; mt < 2; mt++) {
                int rr = wid * 32 + mt * 16 + tg;
                a[mt][0] = sA[rr * 68 + kg + tig];
                a[mt][1] = sA[(rr + 8) * 68 + kg + tig];
                a[mt][2] = sA[rr * 68 + kg + tig + 4];
                a[mt][3] = sA[(rr + 8) * 68 + kg + tig + 4];
            }
            #pragma unroll
            for (int nt = 0; nt < 8; nt++) {
                unsigned b0 = sW[(ko + tig) * 68 + nt * 8 + tg];
                unsigned b1 = sW[(ko + tig + 4) * 68 + nt * 8 + tg];
                mma_tf32(c[0][nt], a[0], b0, b1);
                mma_tf32(c[1][nt], a[1], b0, b1);
            }
        }
    }

    if (!DUAL) {
        // pool epilogue: relu + atomic accumulate
        #pragma unroll
        for (int mt = 0; mt < 2; mt++) {
            int row = row0 + wid * 32 + mt * 16 + tg;
            #pragma unroll
            for (int half_i = 0; half_i < 2; half_i++) {
                int r = row + half_i * 8;
                if (r < N_NODES) {
                    int b = batch[r];
                    #pragma unroll
                    for (int nt = 0; nt < 8; nt++) {
                        int col = nt * 8 + tig * 2;
                        atomicAdd(&g_pool[b * HD + col],
                                  fmaxf(c[mt][nt][half_i * 2 + 0], 0.f));
                        atomicAdd(&g_pool[b * HD + col + 1],
                                  fmaxf(c[mt][nt][half_i * 2 + 1], 0.f));
                    }
                }
            }
        }
        return;
    }

    // ---- relu + write h back into sA (warp-private rows) ----
    #pragma unroll
    for (int mt = 0; mt < 2; mt++) {
        int rlo = wid * 32 + mt * 16 + tg;
        #pragma unroll
        for (int nt = 0; nt < 8; nt++) {
            int col = nt * 8 + 2 * tig;
            uint2 lo, hi;
            lo.x = f2tf(fmaxf(c[mt][nt][0], 0.f));
            lo.y = f2tf(fmaxf(c[mt][nt][1], 0.f));
            hi.x = f2tf(fmaxf(c[mt][nt][2], 0.f));
            hi.y = f2tf(fmaxf(c[mt][nt][3], 0.f));
            *(uint2*)&sA[rlo * 68 + col] = lo;
            *(uint2*)&sA[(rlo + 8) * 68 + col] = hi;
        }
    }
    __syncwarp();
    #pragma unroll
    for (int mt = 0; mt < 2; mt++)
        #pragma unroll
        for (int nt = 0; nt < 8; nt++)
            #pragma unroll
            for (int j = 0; j < 4; j++) c[mt][nt][j] = 0.f;

    // ---- GEMM2: h @ W1next ----
    for (int ch = 0; ch < 4; ch++) {
        __syncthreads();
        #pragma unroll
        for (int it = 0; it < 2; it++) {
            int id = tid + it * 128;
            int k = id >> 4, c4 = id & 15;
            float4 v = *(const float4*)(W1n + (size_t)(ch * 16 + k) * 64 + c4 * 4);
            unsigned* p = &sW[k * 68 + c4 * 4];
            p[0] = f2tf(v.x); p[1] = f2tf(v.y); p[2] = f2tf(v.z); p[3] = f2tf(v.w);
        }
        __syncthreads();
        #pragma unroll
        for (int ks = 0; ks < 2; ks++) {
            int ko = ks * 8;
            int kg = ch * 16 + ko;
            unsigned a[2][4];
            #pragma unroll
            for (int mt = 0; mt < 2; mt++) {
                int rr = wid * 32 + mt * 16 + tg;
                a[mt][0] = sA[rr * 68 + kg + tig];
                a[mt][1] = sA[(rr + 8) * 68 + kg + tig];
                a[mt][2] = sA[rr * 68 + kg + tig + 4];
                a[mt][3] = sA[(rr + 8) * 68 + kg + tig + 4];
            }
            #pragma unroll
            for (int nt = 0; nt < 8; nt++) {
                unsigned b0 = sW[(ko + tig) * 68 + nt * 8 + tg];
                unsigned b1 = sW[(ko + tig + 4) * 68 + nt * 8 + tg];
                mma_tf32(c[0][nt], a[0], b0, b1);
                mma_tf32(c[1][nt], a[1], b0, b1);
            }
        }
    }

    // store y (no relu)
    #pragma unroll
    for (int mt = 0; mt < 2; mt++) {
        int row = row0 + wid * 32 + mt * 16 + tg;
        #pragma unroll
        for (int half_i = 0; half_i < 2; half_i++) {
            int r = row + half_i * 8;
            if (r < N_NODES) {
                #pragma unroll
                for (int nt = 0; nt < 8; nt++) {
                    int col = nt * 8 + tig * 2;
                    *(__half2*)(g_y + (size_t)r * HD + col) =
                        __float22half2_rn(make_float2(c[mt][nt][half_i * 2 + 0],
                                                      c[mt][nt][half_i * 2 + 1]));
                }
            }
        }
    }
}

// ---------------- aggregation + BN + relu (fp16 in/out, fp32 accumulate) ----------
__global__ __launch_bounds__(256) void k_agg(const float* __restrict__ gam,
                                             const float* __restrict__ bet,
                                             const float* __restrict__ mea,
                                             const float* __restrict__ var) {
    int gwarp = (blockIdx.x * 256 + threadIdx.x) >> 5;  // one warp per node
    int lane = threadIdx.x & 31;
    if (gwarp >= N_NODES) return;
    const __half2* yv = (const __half2*)g_y;
    float2 acc = __half22float2(yv[(size_t)gwarp * 32 + lane]);
    int beg = g_rowptr[gwarp], end = g_rowptr[gwarp + 1];
    for (int base = beg; base < end; base += 32) {
        int n = end - base;
        if (n > 32) n = 32;
        int idx = (lane < n) ? g_csrsrc[base + lane] : 0;
        int t = 0;
        for (; t + 4 <= n; t += 4) {
            int s0 = __shfl_sync(0xffffffffu, idx, t + 0);
            int s1 = __shfl_sync(0xffffffffu, idx, t + 1);
            int s2 = __shfl_sync(0xffffffffu, idx, t + 2);
            int s3 = __shfl_sync(0xffffffffu, idx, t + 3);
            float2 v0 = __half22float2(yv[(size_t)s0 * 32 + lane]);
            float2 v1 = __half22float2(yv[(size_t)s1 * 32 + lane]);
            float2 v2 = __half22float2(yv[(size_t)s2 * 32 + lane]);
            float2 v3 = __half22float2(yv[(size_t)s3 * 32 + lane]);
            acc.x += (v0.x + v1.x) + (v2.x + v3.x);
            acc.y += (v0.y + v1.y) + (v2.y + v3.y);
        }
        for (; t < n; t++) {
            int s = __shfl_sync(0xffffffffu, idx, t);
            float2 v = __half22float2(yv[(size_t)s * 32 + lane]);
            acc.x += v.x;
            acc.y += v.y;
        }
    }
    int c0 = lane * 2;
    float i0 = rsqrtf(var[c0] + BN_EPS) * gam[c0];
    float i1 = rsqrtf(var[c0 + 1] + BN_EPS) * gam[c0 + 1];
    float h0 = fmaxf((acc.x - mea[c0]) * i0 + bet[c0], 0.f);
    float h1 = fmaxf((acc.y - mea[c0 + 1]) * i1 + bet[c0 + 1], 0.f);
    ((__half2*)g_a)[(size_t)gwarp * 32 + lane] = __float22half2_rn(make_float2(h0, h1));
}

// ---------------- final head ----------------
__global__ void k_final(const float* __restrict__ lin1, const float* __restrict__ lin2,
                        const float* __restrict__ lb, float* __restrict__ out) {
    __shared__ float sL1[64 * 64];
    __shared__ float sL2[64 * 10];
    __shared__ float sB[10];
    int tid = threadIdx.x;
    for (int i = tid; i < 64 * 64; i += 128) sL1[i] = lin1[i];
    for (int i = tid; i < 64 * 10; i += 128) sL2[i] = lin2[i];
    if (tid < 10) sB[tid] = lb[tid];
    __syncthreads();
    if (tid < N_GRAPHS) {
        float cnt = (float)g_cnt[tid];
        if (cnt < 1.f) cnt = 1.f;
        float pooled[64];
        #pragma unroll
        for (int k = 0; k < 64; k++) pooled[k] = g_pool[tid * 64 + k] / cnt;
        float o[10];
        #pragma unroll
        for (int c = 0; c < 10; c++) o[c] = sB[c];
        for (int j = 0; j < 64; j++) {
            float z = 0.f;
            #pragma unroll
            for (int k = 0; k < 64; k++) z += pooled[k] * sL1[k * 64 + j];
            z = fmaxf(z, 0.f);
            #pragma unroll
            for (int c = 0; c < 10; c++) o[c] += z * sL2[j * 10 + c];
        }
        float mx = o[0];
        #pragma unroll
        for (int c = 1; c < 10; c++) mx = fmaxf(mx, o[c]);
        float se = 0.f;
        #pragma unroll
        for (int c = 0; c < 10; c++) se += expf(o[c] - mx);
        float lse = logf(se) + mx;
        #pragma unroll
        for (int c = 0; c < 10; c++) out[tid * 10 + c] = o[c] - lse;
    }
}

// ---------------- launch (kernel launches ONLY) ----------------
extern "C" void kernel_launch(void* const* d_in, const int* in_sizes, int n_in,
                              void* d_out, int out_size) {
    const float* x      = (const float*)d_in[0];
    const int*   ei     = (const int*)d_in[1];
    const int*   batch  = (const int*)d_in[2];
    const float* W1_0   = (const float*)d_in[3];
    const float* bn_g_0 = (const float*)d_in[4];
    const float* bn_b_0 = (const float*)d_in[5];
    const float* bn_m_0 = (const float*)d_in[6];
    const float* bn_v_0 = (const float*)d_in[7];
    const float* W2_0   = (const float*)d_in[8];
    const float* W1_r   = (const float*)d_in[9];
    const float* bn_g_r = (const float*)d_in[10];
    const float* bn_b_r = (const float*)d_in[11];
    const float* bn_m_r = (const float*)d_in[12];
    const float* bn_v_r = (const float*)d_in[13];
    const float* W2_r   = (const float*)d_in[14];
    const float* lin1   = (const float*)d_in[15];
    const float* lin2   = (const float*)d_in[16];
    const float* lin2b  = (const float*)d_in[17];
    float* out = (float*)d_out;

    const int TPB = 256;
    int gridNodes = (N_NODES + TPB - 1) / TPB;
    int gridEdges = (N_EDGES + TPB - 1) / TPB;
    int gridGemm0 = (N_NODES + 255) / 256;          // 391
    int gridDual = (N_NODES + 127) / 128;           // 782
    int gridAgg = (N_NODES * 32 + TPB - 1) / TPB;   // warp per node

    // CSR build (5 launches)
    k_init<<<gridNodes, TPB>>>();
    k_count<<<gridEdges, TPB>>>(ei, batch);
    k_scan1<<<SCAN_BLK, 1024>>>();
    k_scan23<<<SCAN_BLK, 1024>>>();
    k_scatter<<<gridEdges, TPB>>>(ei);

    // y0 = x @ W1_0
    k_gemm0<<<gridGemm0, TPB>>>(x, W1_0);
    // a0 = relu(BN(y0 + agg(y0)))
    k_agg<<<gridAgg, TPB>>>(bn_g_0, bn_b_0, bn_m_0, bn_v_0);
    // h1 = relu(a0 @ W2_0); y1 = h1 @ W1_r[0]
    k_dual<true><<<gridDual, 128>>>(W2_0, W1_r + 0 * 4096, nullptr);
    k_agg<<<gridAgg, TPB>>>(bn_g_r + 0, bn_b_r + 0, bn_m_r + 0, bn_v_r + 0);
    // h2 = relu(a1 @ W2_r[0]); y2 = h2 @ W1_r[1]
    k_dual<true><<<gridDual, 128>>>(W2_r + 0 * 4096, W1_r + 1 * 4096, nullptr);
    k_agg<<<gridAgg, TPB>>>(bn_g_r + 64, bn_b_r + 64, bn_m_r + 64, bn_v_r + 64);
    // h3 = relu(a2 @ W2_r[1]); y3 = h3 @ W1_r[2]
    k_dual<true><<<gridDual, 128>>>(W2_r + 1 * 4096, W1_r + 2 * 4096, nullptr);
    k_agg<<<gridAgg, TPB>>>(bn_g_r + 128, bn_b_r + 128, bn_m_r + 128, bn_v_r + 128);
    // pool += relu(a3 @ W2_r[2])
    k_dual<false><<<gridDual, 128>>>(W2_r + 2 * 4096, nullptr, batch);

    // head
    k_final<<<1, 128>>>(lin1, lin2, lin2b, out);
}

// round 9
// speedup vs baseline: 1.8634x; 1.0294x over previous
#include <cuda_runtime.h>
#include <cuda_fp16.h>
#include <math.h>

#define N_NODES 100000
#define N_EDGES 1000000
#define N_GRAPHS 128
#define HD 64
#define BN_EPS 1e-5f

#define SCAN_BLK 25            // ceil(100000 / 4096)

// ---------------- scratch (device globals; no allocation allowed) ----------------
// Self-cleaning invariant: every buffer that must start at zero is re-zeroed by
// the kernel that consumes it, so each kernel_launch call leaves the state it
// found (device globals are zero-initialized at load).
__device__ __align__(16) int    g_rowptr[N_NODES + 1];
__device__ __align__(16) int    g_cursor[N_NODES];
__device__ __align__(16) int    g_deg[N_NODES];
__device__ __align__(16) int    g_bsum[SCAN_BLK];
__device__ __align__(16) int    g_csrsrc[N_EDGES];
__device__ __align__(16) __half g_y[N_NODES * HD];
__device__ __align__(16) __half g_a[N_NODES * HD];
__device__ __align__(16) float  g_pool[N_GRAPHS * HD];
__device__ __align__(16) int    g_cnt[N_GRAPHS];

// ---------------- helpers ----------------
__device__ __forceinline__ unsigned f2tf(float f) {
    unsigned u;
    asm("cvt.rna.tf32.f32 %0, %1;" : "=r"(u) : "f"(f));
    return u;
}
__device__ __forceinline__ void mma_tf32(float* c, const unsigned* a,
                                         unsigned b0, unsigned b1) {
    asm("mma.sync.aligned.m16n8k8.row.col.f32.tf32.tf32.f32 "
        "{%0,%1,%2,%3},{%4,%5,%6,%7},{%8,%9},{%0,%1,%2,%3};"
        : "+f"(c[0]), "+f"(c[1]), "+f"(c[2]), "+f"(c[3])
        : "r"(a[0]), "r"(a[1]), "r"(a[2]), "r"(a[3]), "r"(b0), "r"(b1));
}

// ---------------- CSR build ----------------
__global__ void k_count(const int* __restrict__ ei,
                        const int* __restrict__ batch) {
    int e = blockIdx.x * blockDim.x + threadIdx.x;
    if (e < N_EDGES) atomicAdd(&g_deg[ei[N_EDGES + e]], 1);
    if (e < N_NODES) atomicAdd(&g_cnt[batch[e]], 1);
}

// ---- scan phase 1: block-local exclusive scan (4096 elems/block) -> g_cursor, g_bsum
__global__ __launch_bounds__(1024) void k_scan1() {
    __shared__ int warpsum[32];
    int tid = threadIdx.x, lane = tid & 31, wid = tid >> 5;
    int i0 = blockIdx.x * 4096 + tid * 4;
    int4 v = make_int4(0, 0, 0, 0);
    if (i0 + 3 < N_NODES) {
        v = *(const int4*)&g_deg[i0];
    } else {
        if (i0 + 0 < N_NODES) v.x = g_deg[i0 + 0];
        if (i0 + 1 < N_NODES) v.y = g_deg[i0 + 1];
        if (i0 + 2 < N_NODES) v.z = g_deg[i0 + 2];
        if (i0 + 3 < N_NODES) v.w = g_deg[i0 + 3];
    }
    int s = v.x + v.y + v.z + v.w;
    int x = s;
    #pragma unroll
    for (int off = 1; off < 32; off <<= 1) {
        int t = __shfl_up_sync(0xffffffffu, x, off);
        if (lane >= off) x += t;
    }
    if (lane == 31) warpsum[wid] = x;
    __syncthreads();
    if (wid == 0) {
        int w = warpsum[lane];
        #pragma unroll
        for (int off = 1; off < 32; off <<= 1) {
            int t = __shfl_up_sync(0xffffffffu, w, off);
            if (lane >= off) w += t;
        }
        warpsum[lane] = w;
    }
    __syncthreads();
    int woff = (wid > 0) ? warpsum[wid - 1] : 0;
    int excl = woff + (x - s);  // exclusive within block
    int p0 = excl + v.x, p1 = p0 + v.y, p2 = p1 + v.z;
    if (i0 + 0 < N_NODES) g_cursor[i0 + 0] = excl;
    if (i0 + 1 < N_NODES) g_cursor[i0 + 1] = p0;
    if (i0 + 2 < N_NODES) g_cursor[i0 + 2] = p1;
    if (i0 + 3 < N_NODES) g_cursor[i0 + 3] = p2;
    if (tid == 1023) g_bsum[blockIdx.x] = warpsum[31];
}

// ---- scan phase 2+3 merged: each block scans the 25 block sums itself, then
//      adds its offset; emits cursor (mutable) + rowptr (stable).
//      Also re-zeroes g_deg (consumed by scan1) for the next replay. ----
__global__ __launch_bounds__(1024) void k_scan23() {
    __shared__ int s_off;
    int tid = threadIdx.x;
    if (tid < 32) {
        int lane = tid;
        int v = (lane < SCAN_BLK) ? g_bsum[lane] : 0;
        int x = v;
        #pragma unroll
        for (int off = 1; off < 32; off <<= 1) {
            int t = __shfl_up_sync(0xffffffffu, x, off);
            if (lane >= off) x += t;
        }
        if (lane == blockIdx.x) s_off = x - v;
    }
    __syncthreads();
    int off = s_off;
    int i0 = blockIdx.x * 4096 + tid * 4;
    if (i0 + 3 < N_NODES) {
        int4 c = *(const int4*)&g_cursor[i0];
        c.x += off; c.y += off; c.z += off; c.w += off;
        *(int4*)&g_cursor[i0] = c;
        *(int4*)&g_rowptr[i0] = c;
        *(int4*)&g_deg[i0] = make_int4(0, 0, 0, 0);
    } else {
        #pragma unroll
        for (int j = 0; j < 4; j++) {
            if (i0 + j < N_NODES) {
                int c = g_cursor[i0 + j] + off;
                g_cursor[i0 + j] = c;
                g_rowptr[i0 + j] = c;
                g_deg[i0 + j] = 0;
            }
        }
    }
    if (blockIdx.x == 0 && tid == 0) g_rowptr[N_NODES] = N_EDGES;
}

__global__ void k_scatter(const int* __restrict__ ei) {
    int e = blockIdx.x * blockDim.x + threadIdx.x;
    if (e >= N_EDGES) return;
    int d = ei[N_EDGES + e];
    int s = ei[e];
    int p = atomicAdd(&g_cursor[d], 1);
    g_csrsrc[p] = s;
}

// ---------------- layer-0 input GEMM: g_y = x[N,128] @ W1_0[128,64] (TF32) ----
__global__ __launch_bounds__(256) void k_gemm0(const float* __restrict__ A,
                                               const float* __restrict__ W) {
    constexpr int K = 128;
    __shared__ unsigned sA[256 * 17];
    __shared__ unsigned sW[16 * 65];
    int tid = threadIdx.x;
    int wid = tid >> 5, lane = tid & 31;
    int tg = lane >> 2, tig = lane & 3;
    int row0 = blockIdx.x * 256;

    float c[2][8][4];
    #pragma unroll
    for (int mt = 0; mt < 2; mt++)
        #pragma unroll
        for (int nt = 0; nt < 8; nt++)
            #pragma unroll
            for (int j = 0; j < 4; j++) c[mt][nt][j] = 0.f;

    for (int ch = 0; ch < 8; ch++) {
        int kbase = ch * 16;
        #pragma unroll
        for (int i = 0; i < 4; i++) {
            int idx = tid + i * 256;
            int r = idx >> 2, c4 = idx & 3;
            int grow = row0 + r;
            float4 v = make_float4(0.f, 0.f, 0.f, 0.f);
            if (grow < N_NODES)
                v = *(const float4*)(A + (size_t)grow * K + kbase + c4 * 4);
            unsigned* p = &sA[r * 17 + c4 * 4];
            p[0] = f2tf(v.x); p[1] = f2tf(v.y); p[2] = f2tf(v.z); p[3] = f2tf(v.w);
        }
        {
            int k = tid >> 4, c4 = tid & 15;
            float4 v = *(const float4*)(W + (size_t)(kbase + k) * 64 + c4 * 4);
            unsigned* p = &sW[k * 65 + c4 * 4];
            p[0] = f2tf(v.x); p[1] = f2tf(v.y); p[2] = f2tf(v.z); p[3] = f2tf(v.w);
        }
        __syncthreads();
        #pragma unroll
        for (int ks = 0; ks < 2; ks++) {
            int ko = ks * 8;
            unsigned a[2][4];
            #pragma unroll
            for (int mt = 0; mt < 2; mt++) {
                int rr = wid * 32 + mt * 16 + tg;
                a[mt][0] = sA[rr * 17 + ko + tig];
                a[mt][1] = sA[(rr + 8) * 17 + ko + tig];
                a[mt][2] = sA[rr * 17 + ko + tig + 4];
                a[mt][3] = sA[(rr + 8) * 17 + ko + tig + 4];
            }
            #pragma unroll
            for (int nt = 0; nt < 8; nt++) {
                unsigned b0 = sW[(ko + tig) * 65 + nt * 8 + tg];
                unsigned b1 = sW[(ko + tig + 4) * 65 + nt * 8 + tg];
                mma_tf32(c[0][nt], a[0], b0, b1);
                mma_tf32(c[1][nt], a[1], b0, b1);
            }
        }
        __syncthreads();
    }
    #pragma unroll
    for (int mt = 0; mt < 2; mt++) {
        int row = row0 + wid * 32 + mt * 16 + tg;
        #pragma unroll
        for (int half_i = 0; half_i < 2; half_i++) {
            int r = row + half_i * 8;
            if (r < N_NODES) {
                #pragma unroll
                for (int nt = 0; nt < 8; nt++) {
                    int col = nt * 8 + tig * 2;
                    *(__half2*)(g_y + (size_t)r * HD + col) =
                        __float22half2_rn(make_float2(c[mt][nt][half_i * 2 + 0],
                                                      c[mt][nt][half_i * 2 + 1]));
                }
            }
        }
    }
}

// ---------------- chained dual GEMM ----------------
template <bool DUAL>
__global__ __launch_bounds__(128) void k_dual(const float* __restrict__ W2,
                                              const float* __restrict__ W1n,
                                              const int* __restrict__ batch) {
    __shared__ unsigned sA[128 * 68];
    __shared__ unsigned sW[16 * 68];

    int tid = threadIdx.x, wid = tid >> 5, lane = tid & 31;
    int tg = lane >> 2, tig = lane & 3;
    int row0 = blockIdx.x * 128;

    // load A = g_a rows (fp16 -> tf32 in smem)
    #pragma unroll
    for (int i = 0; i < 8; i++) {
        int idx = tid + i * 128;           // 1024 uint4 total
        int r = idx >> 3, seg = idx & 7;   // 8 halves per uint4
        int grow = row0 + r;
        uint4 raw = make_uint4(0u, 0u, 0u, 0u);
        if (grow < N_NODES)
            raw = *(const uint4*)(g_a + (size_t)grow * HD + seg * 8);
        unsigned* p = &sA[r * 68 + seg * 8];
        float2 f;
        f = __half22float2(*(__half2*)&raw.x); p[0] = f2tf(f.x); p[1] = f2tf(f.y);
        f = __half22float2(*(__half2*)&raw.y); p[2] = f2tf(f.x); p[3] = f2tf(f.y);
        f = __half22float2(*(__half2*)&raw.z); p[4] = f2tf(f.x); p[5] = f2tf(f.y);
        f = __half22float2(*(__half2*)&raw.w); p[6] = f2tf(f.x); p[7] = f2tf(f.y);
    }

    float c[2][8][4];
    #pragma unroll
    for (int mt = 0; mt < 2; mt++)
        #pragma unroll
        for (int nt = 0; nt < 8; nt++)
            #pragma unroll
            for (int j = 0; j < 4; j++) c[mt][nt][j] = 0.f;

    // ---- GEMM1: A @ W2 ----
    for (int ch = 0; ch < 4; ch++) {
        __syncthreads();
        #pragma unroll
        for (int it = 0; it < 2; it++) {
            int id = tid + it * 128;
            int k = id >> 4, c4 = id & 15;
            float4 v = *(const float4*)(W2 + (size_t)(ch * 16 + k) * 64 + c4 * 4);
            unsigned* p = &sW[k * 68 + c4 * 4];
            p[0] = f2tf(v.x); p[1] = f2tf(v.y); p[2] = f2tf(v.z); p[3] = f2tf(v.w);
        }
        __syncthreads();
        #pragma unroll
        for (int ks = 0; ks < 2; ks++) {
            int ko = ks * 8;
            int kg = ch * 16 + ko;
            unsigned a[2][4];
            #pragma unroll
            for (int mt = 0; mt < 2; mt++) {
                int rr = wid * 32 + mt * 16 + tg;
                a[mt][0] = sA[rr * 68 + kg + tig];
                a[mt][1] = sA[(rr + 8) * 68 + kg + tig];
                a[mt][2] = sA[rr * 68 + kg + tig + 4];
                a[mt][3] = sA[(rr + 8) * 68 + kg + tig + 4];
            }
            #pragma unroll
            for (int nt = 0; nt < 8; nt++) {
                unsigned b0 = sW[(ko + tig) * 68 + nt * 8 + tg];
                unsigned b1 = sW[(ko + tig + 4) * 68 + nt * 8 + tg];
                mma_tf32(c[0][nt], a[0], b0, b1);
                mma_tf32(c[1][nt], a[1], b0, b1);
            }
        }
    }

    if (!DUAL) {
        #pragma unroll
        for (int mt = 0; mt < 2; mt++) {
            int row = row0 + wid * 32 + mt * 16 + tg;
            #pragma unroll
            for (int half_i = 0; half_i < 2; half_i++) {
                int r = row + half_i * 8;
                if (r < N_NODES) {
                    int b = batch[r];
                    #pragma unroll
                    for (int nt = 0; nt < 8; nt++) {
                        int col = nt * 8 + tig * 2;
                        atomicAdd(&g_pool[b * HD + col],
                                  fmaxf(c[mt][nt][half_i * 2 + 0], 0.f));
                        atomicAdd(&g_pool[b * HD + col + 1],
                                  fmaxf(c[mt][nt][half_i * 2 + 1], 0.f));
                    }
                }
            }
        }
        return;
    }

    // ---- relu + write h back into sA (warp-private rows) ----
    #pragma unroll
    for (int mt = 0; mt < 2; mt++) {
        int rlo = wid * 32 + mt * 16 + tg;
        #pragma unroll
        for (int nt = 0; nt < 8; nt++) {
            int col = nt * 8 + 2 * tig;
            uint2 lo, hi;
            lo.x = f2tf(fmaxf(c[mt][nt][0], 0.f));
            lo.y = f2tf(fmaxf(c[mt][nt][1], 0.f));
            hi.x = f2tf(fmaxf(c[mt][nt][2], 0.f));
            hi.y = f2tf(fmaxf(c[mt][nt][3], 0.f));
            *(uint2*)&sA[rlo * 68 + col] = lo;
            *(uint2*)&sA[(rlo + 8) * 68 + col] = hi;
        }
    }
    __syncwarp();
    #pragma unroll
    for (int mt = 0; mt < 2; mt++)
        #pragma unroll
        for (int nt = 0; nt < 8; nt++)
            #pragma unroll
            for (int j = 0; j < 4; j++) c[mt][nt][j] = 0.f;

    // ---- GEMM2: h @ W1next ----
    for (int ch = 0; ch < 4; ch++) {
        __syncthreads();
        #pragma unroll
        for (int it = 0; it < 2; it++) {
            int id = tid + it * 128;
            int k = id >> 4, c4 = id & 15;
            float4 v = *(const float4*)(W1n + (size_t)(ch * 16 + k) * 64 + c4 * 4);
            unsigned* p = &sW[k * 68 + c4 * 4];
            p[0] = f2tf(v.x); p[1] = f2tf(v.y); p[2] = f2tf(v.z); p[3] = f2tf(v.w);
        }
        __syncthreads();
        #pragma unroll
        for (int ks = 0; ks < 2; ks++) {
            int ko = ks * 8;
            int kg = ch * 16 + ko;
            unsigned a[2][4];
            #pragma unroll
            for (int mt = 0; mt < 2; mt++) {
                int rr = wid * 32 + mt * 16 + tg;
                a[mt][0] = sA[rr * 68 + kg + tig];
                a[mt][1] = sA[(rr + 8) * 68 + kg + tig];
                a[mt][2] = sA[rr * 68 + kg + tig + 4];
                a[mt][3] = sA[(rr + 8) * 68 + kg + tig + 4];
            }
            #pragma unroll
            for (int nt = 0; nt < 8; nt++) {
                unsigned b0 = sW[(ko + tig) * 68 + nt * 8 + tg];
                unsigned b1 = sW[(ko + tig + 4) * 68 + nt * 8 + tg];
                mma_tf32(c[0][nt], a[0], b0, b1);
                mma_tf32(c[1][nt], a[1], b0, b1);
            }
        }
    }

    // store y (no relu)
    #pragma unroll
    for (int mt = 0; mt < 2; mt++) {
        int row = row0 + wid * 32 + mt * 16 + tg;
        #pragma unroll
        for (int half_i = 0; half_i < 2; half_i++) {
            int r = row + half_i * 8;
            if (r < N_NODES) {
                #pragma unroll
                for (int nt = 0; nt < 8; nt++) {
                    int col = nt * 8 + tig * 2;
                    *(__half2*)(g_y + (size_t)r * HD + col) =
                        __float22half2_rn(make_float2(c[mt][nt][half_i * 2 + 0],
                                                      c[mt][nt][half_i * 2 + 1]));
                }
            }
        }
    }
}

// ---------------- aggregation + BN + relu (fp16 in/out, fp32 accumulate) ----------
__global__ __launch_bounds__(256) void k_agg(const float* __restrict__ gam,
                                             const float* __restrict__ bet,
                                             const float* __restrict__ mea,
                                             const float* __restrict__ var) {
    int gwarp = (blockIdx.x * 256 + threadIdx.x) >> 5;  // one warp per node
    int lane = threadIdx.x & 31;
    if (gwarp >= N_NODES) return;
    const __half2* yv = (const __half2*)g_y;
    float2 acc = __half22float2(yv[(size_t)gwarp * 32 + lane]);
    int beg = g_rowptr[gwarp], end = g_rowptr[gwarp + 1];
    for (int base = beg; base < end; base += 32) {
        int n = end - base;
        if (n > 32) n = 32;
        int idx = (lane < n) ? g_csrsrc[base + lane] : 0;
        int t = 0;
        for (; t + 4 <= n; t += 4) {
            int s0 = __shfl_sync(0xffffffffu, idx, t + 0);
            int s1 = __shfl_sync(0xffffffffu, idx, t + 1);
            int s2 = __shfl_sync(0xffffffffu, idx, t + 2);
            int s3 = __shfl_sync(0xffffffffu, idx, t + 3);
            float2 v0 = __half22float2(yv[(size_t)s0 * 32 + lane]);
            float2 v1 = __half22float2(yv[(size_t)s1 * 32 + lane]);
            float2 v2 = __half22float2(yv[(size_t)s2 * 32 + lane]);
            float2 v3 = __half22float2(yv[(size_t)s3 * 32 + lane]);
            acc.x += (v0.x + v1.x) + (v2.x + v3.x);
            acc.y += (v0.y + v1.y) + (v2.y + v3.y);
        }
        for (; t < n; t++) {
            int s = __shfl_sync(0xffffffffu, idx, t);
            float2 v = __half22float2(yv[(size_t)s * 32 + lane]);
            acc.x += v.x;
            acc.y += v.y;
        }
    }
    int c0 = lane * 2;
    float i0 = rsqrtf(var[c0] + BN_EPS) * gam[c0];
    float i1 = rsqrtf(var[c0 + 1] + BN_EPS) * gam[c0 + 1];
    float h0 = fmaxf((acc.x - mea[c0]) * i0 + bet[c0], 0.f);
    float h1 = fmaxf((acc.y - mea[c0 + 1]) * i1 + bet[c0 + 1], 0.f);
    ((__half2*)g_a)[(size_t)gwarp * 32 + lane] = __float22half2_rn(make_float2(h0, h1));
}

// ---------------- final head (also self-cleans g_pool / g_cnt) ----------------
__global__ void k_final(const float* __restrict__ lin1, const float* __restrict__ lin2,
                        const float* __restrict__ lb, float* __restrict__ out) {
    __shared__ float sL1[64 * 64];
    __shared__ float sL2[64 * 10];
    __shared__ float sB[10];
    int tid = threadIdx.x;
    for (int i = tid; i < 64 * 64; i += 128) sL1[i] = lin1[i];
    for (int i = tid; i < 64 * 10; i += 128) sL2[i] = lin2[i];
    if (tid < 10) sB[tid] = lb[tid];
    __syncthreads();
    if (tid < N_GRAPHS) {
        float cnt = (float)g_cnt[tid];
        if (cnt < 1.f) cnt = 1.f;
        float pooled[64];
        #pragma unroll
        for (int k = 0; k < 64; k++) {
            pooled[k] = g_pool[tid * 64 + k] / cnt;
            g_pool[tid * 64 + k] = 0.f;   // self-clean for next replay
        }
        g_cnt[tid] = 0;                   // self-clean
        float o[10];
        #pragma unroll
        for (int c = 0; c < 10; c++) o[c] = sB[c];
        for (int j = 0; j < 64; j++) {
            float z = 0.f;
            #pragma unroll
            for (int k = 0; k < 64; k++) z += pooled[k] * sL1[k * 64 + j];
            z = fmaxf(z, 0.f);
            #pragma unroll
            for (int c = 0; c < 10; c++) o[c] += z * sL2[j * 10 + c];
        }
        float mx = o[0];
        #pragma unroll
        for (int c = 1; c < 10; c++) mx = fmaxf(mx, o[c]);
        float se = 0.f;
        #pragma unroll
        for (int c = 0; c < 10; c++) se += expf(o[c] - mx);
        float lse = logf(se) + mx;
        #pragma unroll
        for (int c = 0; c < 10; c++) out[tid * 10 + c] = o[c] - lse;
    }
}

// ---------------- launch ----------------
extern "C" void kernel_launch(void* const* d_in, const int* in_sizes, int n_in,
                              void* d_out, int out_size) {
    const float* x      = (const float*)d_in[0];
    const int*   ei     = (const int*)d_in[1];
    const int*   batch  = (const int*)d_in[2];
    const float* W1_0   = (const float*)d_in[3];
    const float* bn_g_0 = (const float*)d_in[4];
    const float* bn_b_0 = (const float*)d_in[5];
    const float* bn_m_0 = (const float*)d_in[6];
    const float* bn_v_0 = (const float*)d_in[7];
    const float* W2_0   = (const float*)d_in[8];
    const float* W1_r   = (const float*)d_in[9];
    const float* bn_g_r = (const float*)d_in[10];
    const float* bn_b_r = (const float*)d_in[11];
    const float* bn_m_r = (const float*)d_in[12];
    const float* bn_v_r = (const float*)d_in[13];
    const float* W2_r   = (const float*)d_in[14];
    const float* lin1   = (const float*)d_in[15];
    const float* lin2   = (const float*)d_in[16];
    const float* lin2b  = (const float*)d_in[17];
    float* out = (float*)d_out;

    const int TPB = 256;
    int gridEdges = (N_EDGES + TPB - 1) / TPB;
    int gridGemm0 = (N_NODES + 255) / 256;          // 391
    int gridDual = (N_NODES + 127) / 128;           // 782
    int gridAgg = (N_NODES * 32 + TPB - 1) / TPB;   // warp per node

    // fork: gemm0 (depends only on inputs) runs concurrently with CSR build
    cudaStream_t side;
    cudaStreamCreateWithFlags(&side, cudaStreamNonBlocking);
    cudaEvent_t evFork, evJoin;
    cudaEventCreateWithFlags(&evFork, cudaEventDisableTiming);
    cudaEventCreateWithFlags(&evJoin, cudaEventDisableTiming);

    cudaEventRecord(evFork, 0);
    cudaStreamWaitEvent(side, evFork, 0);
    k_gemm0<<<gridGemm0, TPB, 0, side>>>(x, W1_0);     // y0 = x @ W1_0
    cudaEventRecord(evJoin, side);

    // CSR build on main stream (g_deg / g_cnt pre-zeroed by self-cleaning)
    k_count<<<gridEdges, TPB>>>(ei, batch);
    k_scan1<<<SCAN_BLK, 1024>>>();
    k_scan23<<<SCAN_BLK, 1024>>>();
    k_scatter<<<gridEdges, TPB>>>(ei);

    cudaStreamWaitEvent(0, evJoin, 0);                 // join before agg

    // a0 = relu(BN(y0 + agg(y0)))
    k_agg<<<gridAgg, TPB>>>(bn_g_0, bn_b_0, bn_m_0, bn_v_0);
    // h1 = relu(a0 @ W2_0); y1 = h1 @ W1_r[0]
    k_dual<true><<<gridDual, 128>>>(W2_0, W1_r + 0 * 4096, nullptr);
    k_agg<<<gridAgg, TPB>>>(bn_g_r + 0, bn_b_r + 0, bn_m_r + 0, bn_v_r + 0);
    k_dual<true><<<gridDual, 128>>>(W2_r + 0 * 4096, W1_r + 1 * 4096, nullptr);
    k_agg<<<gridAgg, TPB>>>(bn_g_r + 64, bn_b_r + 64, bn_m_r + 64, bn_v_r + 64);
    k_dual<true><<<gridDual, 128>>>(W2_r + 1 * 4096, W1_r + 2 * 4096, nullptr);
    k_agg<<<gridAgg, TPB>>>(bn_g_r + 128, bn_b_r + 128, bn_m_r + 128, bn_v_r + 128);
    // pool += relu(a3 @ W2_r[2])
    k_dual<false><<<gridDual, 128>>>(W2_r + 2 * 4096, nullptr, batch);

    // head (self-cleans pool/cnt)
    k_final<<<1, 128>>>(lin1, lin2, lin2b, out);

    cudaStreamDestroy(side);
    cudaEventDestroy(evFork);
    cudaEventDestroy(evJoin);
}

// round 10
// speedup vs baseline: 2.0658x; 1.1086x over previous
#include <cuda_runtime.h>
#include <cuda_fp16.h>
#include <math.h>

#define N_NODES 100000
#define N_EDGES 1000000
#define N_GRAPHS 128
#define HD 64
#define BN_EPS 1e-5f

#define SCAN_BLK 25            // ceil(100000 / 4096)

// ---------------- scratch (device globals; no allocation allowed) ----------------
// Self-cleaning invariant: every buffer that must start at zero is re-zeroed by
// the kernel that consumes it.
__device__ __align__(16) int    g_rowptr[N_NODES + 1];
__device__ __align__(16) int    g_cursor[N_NODES];
__device__ __align__(16) int    g_deg[N_NODES];
__device__ __align__(16) int    g_bsum[SCAN_BLK];
__device__ __align__(16) int    g_csrsrc[N_EDGES];
__device__ __align__(16) __half g_y[N_NODES * HD];
__device__ __align__(16) __half g_a[N_NODES * HD];
__device__ __align__(16) float  g_pool[N_GRAPHS * HD];
__device__ __align__(16) int    g_cnt[N_GRAPHS];

// ---------------- helpers ----------------
__device__ __forceinline__ unsigned f2tf(float f) {
    unsigned u;
    asm("cvt.rna.tf32.f32 %0, %1;" : "=r"(u) : "f"(f));
    return u;
}
__device__ __forceinline__ void mma_tf32(float* c, const unsigned* a,
                                         unsigned b0, unsigned b1) {
    asm("mma.sync.aligned.m16n8k8.row.col.f32.tf32.tf32.f32 "
        "{%0,%1,%2,%3},{%4,%5,%6,%7},{%8,%9},{%0,%1,%2,%3};"
        : "+f"(c[0]), "+f"(c[1]), "+f"(c[2]), "+f"(c[3])
        : "r"(a[0]), "r"(a[1]), "r"(a[2]), "r"(a[3]), "r"(b0), "r"(b1));
}

// ---------------- CSR build ----------------
__global__ void k_count(const int* __restrict__ ei,
                        const int* __restrict__ batch) {
    int e = blockIdx.x * blockDim.x + threadIdx.x;
    if (e < N_EDGES) atomicAdd(&g_deg[ei[N_EDGES + e]], 1);
    if (e < N_NODES) atomicAdd(&g_cnt[batch[e]], 1);
}

__global__ __launch_bounds__(1024) void k_scan1() {
    __shared__ int warpsum[32];
    int tid = threadIdx.x, lane = tid & 31, wid = tid >> 5;
    int i0 = blockIdx.x * 4096 + tid * 4;
    int4 v = make_int4(0, 0, 0, 0);
    if (i0 + 3 < N_NODES) {
        v = *(const int4*)&g_deg[i0];
    } else {
        if (i0 + 0 < N_NODES) v.x = g_deg[i0 + 0];
        if (i0 + 1 < N_NODES) v.y = g_deg[i0 + 1];
        if (i0 + 2 < N_NODES) v.z = g_deg[i0 + 2];
        if (i0 + 3 < N_NODES) v.w = g_deg[i0 + 3];
    }
    int s = v.x + v.y + v.z + v.w;
    int x = s;
    #pragma unroll
    for (int off = 1; off < 32; off <<= 1) {
        int t = __shfl_up_sync(0xffffffffu, x, off);
        if (lane >= off) x += t;
    }
    if (lane == 31) warpsum[wid] = x;
    __syncthreads();
    if (wid == 0) {
        int w = warpsum[lane];
        #pragma unroll
        for (int off = 1; off < 32; off <<= 1) {
            int t = __shfl_up_sync(0xffffffffu, w, off);
            if (lane >= off) w += t;
        }
        warpsum[lane] = w;
    }
    __syncthreads();
    int woff = (wid > 0) ? warpsum[wid - 1] : 0;
    int excl = woff + (x - s);
    int p0 = excl + v.x, p1 = p0 + v.y, p2 = p1 + v.z;
    if (i0 + 0 < N_NODES) g_cursor[i0 + 0] = excl;
    if (i0 + 1 < N_NODES) g_cursor[i0 + 1] = p0;
    if (i0 + 2 < N_NODES) g_cursor[i0 + 2] = p1;
    if (i0 + 3 < N_NODES) g_cursor[i0 + 3] = p2;
    if (tid == 1023) g_bsum[blockIdx.x] = warpsum[31];
}

__global__ __launch_bounds__(1024) void k_scan23() {
    __shared__ int s_off;
    int tid = threadIdx.x;
    if (tid < 32) {
        int lane = tid;
        int v = (lane < SCAN_BLK) ? g_bsum[lane] : 0;
        int x = v;
        #pragma unroll
        for (int off = 1; off < 32; off <<= 1) {
            int t = __shfl_up_sync(0xffffffffu, x, off);
            if (lane >= off) x += t;
        }
        if (lane == blockIdx.x) s_off = x - v;
    }
    __syncthreads();
    int off = s_off;
    int i0 = blockIdx.x * 4096 + tid * 4;
    if (i0 + 3 < N_NODES) {
        int4 c = *(const int4*)&g_cursor[i0];
        c.x += off; c.y += off; c.z += off; c.w += off;
        *(int4*)&g_cursor[i0] = c;
        *(int4*)&g_rowptr[i0] = c;
        *(int4*)&g_deg[i0] = make_int4(0, 0, 0, 0);
    } else {
        #pragma unroll
        for (int j = 0; j < 4; j++) {
            if (i0 + j < N_NODES) {
                int c = g_cursor[i0 + j] + off;
                g_cursor[i0 + j] = c;
                g_rowptr[i0 + j] = c;
                g_deg[i0 + j] = 0;
            }
        }
    }
    if (blockIdx.x == 0 && tid == 0) g_rowptr[N_NODES] = N_EDGES;
}

__global__ void k_scatter(const int* __restrict__ ei) {
    int e = blockIdx.x * blockDim.x + threadIdx.x;
    if (e >= N_EDGES) return;
    int d = ei[N_EDGES + e];
    int s = ei[e];
    int p = atomicAdd(&g_cursor[d], 1);
    g_csrsrc[p] = s;
}

// ---------------- layer-0 input GEMM: g_y = x[N,128] @ W1_0[128,64] (TF32) ----
__global__ __launch_bounds__(256) void k_gemm0(const float* __restrict__ A,
                                               const float* __restrict__ W) {
    constexpr int K = 128;
    __shared__ unsigned sA[256 * 17];
    __shared__ unsigned sW[16 * 65];
    int tid = threadIdx.x;
    int wid = tid >> 5, lane = tid & 31;
    int tg = lane >> 2, tig = lane & 3;
    int row0 = blockIdx.x * 256;

    float c[2][8][4];
    #pragma unroll
    for (int mt = 0; mt < 2; mt++)
        #pragma unroll
        for (int nt = 0; nt < 8; nt++)
            #pragma unroll
            for (int j = 0; j < 4; j++) c[mt][nt][j] = 0.f;

    for (int ch = 0; ch < 8; ch++) {
        int kbase = ch * 16;
        #pragma unroll
        for (int i = 0; i < 4; i++) {
            int idx = tid + i * 256;
            int r = idx >> 2, c4 = idx & 3;
            int grow = row0 + r;
            float4 v = make_float4(0.f, 0.f, 0.f, 0.f);
            if (grow < N_NODES)
                v = *(const float4*)(A + (size_t)grow * K + kbase + c4 * 4);
            unsigned* p = &sA[r * 17 + c4 * 4];
            p[0] = f2tf(v.x); p[1] = f2tf(v.y); p[2] = f2tf(v.z); p[3] = f2tf(v.w);
        }
        {
            int k = tid >> 4, c4 = tid & 15;
            float4 v = *(const float4*)(W + (size_t)(kbase + k) * 64 + c4 * 4);
            unsigned* p = &sW[k * 65 + c4 * 4];
            p[0] = f2tf(v.x); p[1] = f2tf(v.y); p[2] = f2tf(v.z); p[3] = f2tf(v.w);
        }
        __syncthreads();
        #pragma unroll
        for (int ks = 0; ks < 2; ks++) {
            int ko = ks * 8;
            unsigned a[2][4];
            #pragma unroll
            for (int mt = 0; mt < 2; mt++) {
                int rr = wid * 32 + mt * 16 + tg;
                a[mt][0] = sA[rr * 17 + ko + tig];
                a[mt][1] = sA[(rr + 8) * 17 + ko + tig];
                a[mt][2] = sA[rr * 17 + ko + tig + 4];
                a[mt][3] = sA[(rr + 8) * 17 + ko + tig + 4];
            }
            #pragma unroll
            for (int nt = 0; nt < 8; nt++) {
                unsigned b0 = sW[(ko + tig) * 65 + nt * 8 + tg];
                unsigned b1 = sW[(ko + tig + 4) * 65 + nt * 8 + tg];
                mma_tf32(c[0][nt], a[0], b0, b1);
                mma_tf32(c[1][nt], a[1], b0, b1);
            }
        }
        __syncthreads();
    }
    #pragma unroll
    for (int mt = 0; mt < 2; mt++) {
        int row = row0 + wid * 32 + mt * 16 + tg;
        #pragma unroll
        for (int half_i = 0; half_i < 2; half_i++) {
            int r = row + half_i * 8;
            if (r < N_NODES) {
                #pragma unroll
                for (int nt = 0; nt < 8; nt++) {
                    int col = nt * 8 + tig * 2;
                    *(__half2*)(g_y + (size_t)r * HD + col) =
                        __float22half2_rn(make_float2(c[mt][nt][half_i * 2 + 0],
                                                      c[mt][nt][half_i * 2 + 1]));
                }
            }
        }
    }
}

// ---------------- chained dual GEMM (unchanged from R9) ----------------
template <bool DUAL>
__global__ __launch_bounds__(128) void k_dual(const float* __restrict__ W2,
                                              const float* __restrict__ W1n,
                                              const int* __restrict__ batch) {
    __shared__ unsigned sA[128 * 68];
    __shared__ unsigned sW[16 * 68];

    int tid = threadIdx.x, wid = tid >> 5, lane = tid & 31;
    int tg = lane >> 2, tig = lane & 3;
    int row0 = blockIdx.x * 128;

    #pragma unroll
    for (int i = 0; i < 8; i++) {
        int idx = tid + i * 128;
        int r = idx >> 3, seg = idx & 7;
        int grow = row0 + r;
        uint4 raw = make_uint4(0u, 0u, 0u, 0u);
        if (grow < N_NODES)
            raw = *(const uint4*)(g_a + (size_t)grow * HD + seg * 8);
        unsigned* p = &sA[r * 68 + seg * 8];
        float2 f;
        f = __half22float2(*(__half2*)&raw.x); p[0] = f2tf(f.x); p[1] = f2tf(f.y);
        f = __half22float2(*(__half2*)&raw.y); p[2] = f2tf(f.x); p[3] = f2tf(f.y);
        f = __half22float2(*(__half2*)&raw.z); p[4] = f2tf(f.x); p[5] = f2tf(f.y);
        f = __half22float2(*(__half2*)&raw.w); p[6] = f2tf(f.x); p[7] = f2tf(f.y);
    }

    float c[2][8][4];
    #pragma unroll
    for (int mt = 0; mt < 2; mt++)
        #pragma unroll
        for (int nt = 0; nt < 8; nt++)
            #pragma unroll
            for (int j = 0; j < 4; j++) c[mt][nt][j] = 0.f;

    for (int ch = 0; ch < 4; ch++) {
        __syncthreads();
        #pragma unroll
        for (int it = 0; it < 2; it++) {
            int id = tid + it * 128;
            int k = id >> 4, c4 = id & 15;
            float4 v = *(const float4*)(W2 + (size_t)(ch * 16 + k) * 64 + c4 * 4);
            unsigned* p = &sW[k * 68 + c4 * 4];
            p[0] = f2tf(v.x); p[1] = f2tf(v.y); p[2] = f2tf(v.z); p[3] = f2tf(v.w);
        }
        __syncthreads();
        #pragma unroll
        for (int ks = 0; ks < 2; ks++) {
            int ko = ks * 8;
            int kg = ch * 16 + ko;
            unsigned a[2][4];
            #pragma unroll
            for (int mt = 0; mt < 2; mt++) {
                int rr = wid * 32 + mt * 16 + tg;
                a[mt][0] = sA[rr * 68 + kg + tig];
                a[mt][1] = sA[(rr + 8) * 68 + kg + tig];
                a[mt][2] = sA[rr * 68 + kg + tig + 4];
                a[mt][3] = sA[(rr + 8) * 68 + kg + tig + 4];
            }
            #pragma unroll
            for (int nt = 0; nt < 8; nt++) {
                unsigned b0 = sW[(ko + tig) * 68 + nt * 8 + tg];
                unsigned b1 = sW[(ko + tig + 4) * 68 + nt * 8 + tg];
                mma_tf32(c[0][nt], a[0], b0, b1);
                mma_tf32(c[1][nt], a[1], b0, b1);
            }
        }
    }

    if (!DUAL) {
        #pragma unroll
        for (int mt = 0; mt < 2; mt++) {
            int row = row0 + wid * 32 + mt * 16 + tg;
            #pragma unroll
            for (int half_i = 0; half_i < 2; half_i++) {
                int r = row + half_i * 8;
                if (r < N_NODES) {
                    int b = batch[r];
                    #pragma unroll
                    for (int nt = 0; nt < 8; nt++) {
                        int col = nt * 8 + tig * 2;
                        atomicAdd(&g_pool[b * HD + col],
                                  fmaxf(c[mt][nt][half_i * 2 + 0], 0.f));
                        atomicAdd(&g_pool[b * HD + col + 1],
                                  fmaxf(c[mt][nt][half_i * 2 + 1], 0.f));
                    }
                }
            }
        }
        return;
    }

    #pragma unroll
    for (int mt = 0; mt < 2; mt++) {
        int rlo = wid * 32 + mt * 16 + tg;
        #pragma unroll
        for (int nt = 0; nt < 8; nt++) {
            int col = nt * 8 + 2 * tig;
            uint2 lo, hi;
            lo.x = f2tf(fmaxf(c[mt][nt][0], 0.f));
            lo.y = f2tf(fmaxf(c[mt][nt][1], 0.f));
            hi.x = f2tf(fmaxf(c[mt][nt][2], 0.f));
            hi.y = f2tf(fmaxf(c[mt][nt][3], 0.f));
            *(uint2*)&sA[rlo * 68 + col] = lo;
            *(uint2*)&sA[(rlo + 8) * 68 + col] = hi;
        }
    }
    __syncwarp();
    #pragma unroll
    for (int mt = 0; mt < 2; mt++)
        #pragma unroll
        for (int nt = 0; nt < 8; nt++)
            #pragma unroll
            for (int j = 0; j < 4; j++) c[mt][nt][j] = 0.f;

    for (int ch = 0; ch < 4; ch++) {
        __syncthreads();
        #pragma unroll
        for (int it = 0; it < 2; it++) {
            int id = tid + it * 128;
            int k = id >> 4, c4 = id & 15;
            float4 v = *(const float4*)(W1n + (size_t)(ch * 16 + k) * 64 + c4 * 4);
            unsigned* p = &sW[k * 68 + c4 * 4];
            p[0] = f2tf(v.x); p[1] = f2tf(v.y); p[2] = f2tf(v.z); p[3] = f2tf(v.w);
        }
        __syncthreads();
        #pragma unroll
        for (int ks = 0; ks < 2; ks++) {
            int ko = ks * 8;
            int kg = ch * 16 + ko;
            unsigned a[2][4];
            #pragma unroll
            for (int mt = 0; mt < 2; mt++) {
                int rr = wid * 32 + mt * 16 + tg;
                a[mt][0] = sA[rr * 68 + kg + tig];
                a[mt][1] = sA[(rr + 8) * 68 + kg + tig];
                a[mt][2] = sA[rr * 68 + kg + tig + 4];
                a[mt][3] = sA[(rr + 8) * 68 + kg + tig + 4];
            }
            #pragma unroll
            for (int nt = 0; nt < 8; nt++) {
                unsigned b0 = sW[(ko + tig) * 68 + nt * 8 + tg];
                unsigned b1 = sW[(ko + tig + 4) * 68 + nt * 8 + tg];
                mma_tf32(c[0][nt], a[0], b0, b1);
                mma_tf32(c[1][nt], a[1], b0, b1);
            }
        }
    }

    #pragma unroll
    for (int mt = 0; mt < 2; mt++) {
        int row = row0 + wid * 32 + mt * 16 + tg;
        #pragma unroll
        for (int half_i = 0; half_i < 2; half_i++) {
            int r = row + half_i * 8;
            if (r < N_NODES) {
                #pragma unroll
                for (int nt = 0; nt < 8; nt++) {
                    int col = nt * 8 + tig * 2;
                    *(__half2*)(g_y + (size_t)r * HD + col) =
                        __float22half2_rn(make_float2(c[mt][nt][half_i * 2 + 0],
                                                      c[mt][nt][half_i * 2 + 1]));
                }
            }
        }
    }
}

// ---------------- aggregation + BN + relu: TWO nodes per warp ----------------
// lanes 0-15 -> node 2w, lanes 16-31 -> node 2w+1; each lane covers 4 cols (uint2).
// Both nodes' dependent-load chains interleave in one instruction stream -> 2x MLP.
__global__ __launch_bounds__(256) void k_agg(const float* __restrict__ gam,
                                             const float* __restrict__ bet,
                                             const float* __restrict__ mea,
                                             const float* __restrict__ var) {
    __shared__ float sScale[64], sShift[64];
    int tid = threadIdx.x;
    if (tid < 64) {
        float sc = rsqrtf(var[tid] + BN_EPS) * gam[tid];
        sScale[tid] = sc;
        sShift[tid] = bet[tid] - mea[tid] * sc;
    }
    __syncthreads();

    int gw = (blockIdx.x * 256 + tid) >> 5;
    if (gw >= N_NODES / 2) return;
    int lane = tid & 31;
    int half = lane >> 4;      // which node this lane serves
    int sub = lane & 15;       // 4-col segment within the row
    int node = 2 * gw + half;

    const uint2* yv = (const uint2*)g_y;   // 16 uint2 per 64-half row

    // self row
    uint2 raw = yv[(size_t)node * 16 + sub];
    float2 fa = __half22float2(*(__half2*)&raw.x);
    float2 fb = __half22float2(*(__half2*)&raw.y);
    float a0 = fa.x, a1 = fa.y, a2 = fb.x, a3 = fb.y;

    int b = g_rowptr[node];
    int end = g_rowptr[node + 1];

    while (__any_sync(0xffffffffu, b < end)) {
        int n = end - b;
        if (n > 16) n = 16;
        if (n < 0) n = 0;
        // idx=0 for inactive slots -> safe dummy loads of row 0
        int idx = (sub < n) ? g_csrsrc[b + sub] : 0;
        int other = __shfl_xor_sync(0xffffffffu, n, 16);
        int m = n > other ? n : other;
        int srcbase = half * 16;
        int t = 0;
        for (; t + 4 <= m; t += 4) {
            int s0 = __shfl_sync(0xffffffffu, idx, srcbase + t + 0);
            int s1 = __shfl_sync(0xffffffffu, idx, srcbase + t + 1);
            int s2 = __shfl_sync(0xffffffffu, idx, srcbase + t + 2);
            int s3 = __shfl_sync(0xffffffffu, idx, srcbase + t + 3);
            uint2 r0 = yv[(size_t)s0 * 16 + sub];
            uint2 r1 = yv[(size_t)s1 * 16 + sub];
            uint2 r2 = yv[(size_t)s2 * 16 + sub];
            uint2 r3 = yv[(size_t)s3 * 16 + sub];
            if (t + 0 < n) {
                float2 u = __half22float2(*(__half2*)&r0.x);
                float2 v2_ = __half22float2(*(__half2*)&r0.y);
                a0 += u.x; a1 += u.y; a2 += v2_.x; a3 += v2_.y;
            }
            if (t + 1 < n) {
                float2 u = __half22float2(*(__half2*)&r1.x);
                float2 v2_ = __half22float2(*(__half2*)&r1.y);
                a0 += u.x; a1 += u.y; a2 += v2_.x; a3 += v2_.y;
            }
            if (t + 2 < n) {
                float2 u = __half22float2(*(__half2*)&r2.x);
                float2 v2_ = __half22float2(*(__half2*)&r2.y);
                a0 += u.x; a1 += u.y; a2 += v2_.x; a3 += v2_.y;
            }
            if (t + 3 < n) {
                float2 u = __half22float2(*(__half2*)&r3.x);
                float2 v2_ = __half22float2(*(__half2*)&r3.y);
                a0 += u.x; a1 += u.y; a2 += v2_.x; a3 += v2_.y;
            }
        }
        for (; t < m; t++) {
            int s = __shfl_sync(0xffffffffu, idx, srcbase + t);
            uint2 r = yv[(size_t)s * 16 + sub];
            if (t < n) {
                float2 u = __half22float2(*(__half2*)&r.x);
                float2 v2_ = __half22float2(*(__half2*)&r.y);
                a0 += u.x; a1 += u.y; a2 += v2_.x; a3 += v2_.y;
            }
        }
        b += 16;
    }

    // BN + relu on 4 columns
    int c0 = sub * 4;
    float4 sc = *(float4*)&sScale[c0];
    float4 sh = *(float4*)&sShift[c0];
    float h0 = fmaxf(fmaf(a0, sc.x, sh.x), 0.f);
    float h1 = fmaxf(fmaf(a1, sc.y, sh.y), 0.f);
    float h2 = fmaxf(fmaf(a2, sc.z, sh.z), 0.f);
    float h3 = fmaxf(fmaf(a3, sc.w, sh.w), 0.f);
    uint2 outv;
    *(__half2*)&outv.x = __float22half2_rn(make_float2(h0, h1));
    *(__half2*)&outv.y = __float22half2_rn(make_float2(h2, h3));
    ((uint2*)g_a)[(size_t)node * 16 + sub] = outv;
}

// ---------------- final head (self-cleans g_pool / g_cnt) ----------------
__global__ void k_final(const float* __restrict__ lin1, const float* __restrict__ lin2,
                        const float* __restrict__ lb, float* __restrict__ out) {
    __shared__ float sL1[64 * 64];
    __shared__ float sL2[64 * 10];
    __shared__ float sB[10];
    int tid = threadIdx.x;
    for (int i = tid; i < 64 * 64; i += 128) sL1[i] = lin1[i];
    for (int i = tid; i < 64 * 10; i += 128) sL2[i] = lin2[i];
    if (tid < 10) sB[tid] = lb[tid];
    __syncthreads();
    if (tid < N_GRAPHS) {
        float cnt = (float)g_cnt[tid];
        if (cnt < 1.f) cnt = 1.f;
        float pooled[64];
        #pragma unroll
        for (int k = 0; k < 64; k++) {
            pooled[k] = g_pool[tid * 64 + k] / cnt;
            g_pool[tid * 64 + k] = 0.f;
        }
        g_cnt[tid] = 0;
        float o[10];
        #pragma unroll
        for (int c = 0; c < 10; c++) o[c] = sB[c];
        for (int j = 0; j < 64; j++) {
            float z = 0.f;
            #pragma unroll
            for (int k = 0; k < 64; k++) z += pooled[k] * sL1[k * 64 + j];
            z = fmaxf(z, 0.f);
            #pragma unroll
            for (int c = 0; c < 10; c++) o[c] += z * sL2[j * 10 + c];
        }
        float mx = o[0];
        #pragma unroll
        for (int c = 1; c < 10; c++) mx = fmaxf(mx, o[c]);
        float se = 0.f;
        #pragma unroll
        for (int c = 0; c < 10; c++) se += expf(o[c] - mx);
        float lse = logf(se) + mx;
        #pragma unroll
        for (int c = 0; c < 10; c++) out[tid * 10 + c] = o[c] - lse;
    }
}

// ---------------- launch ----------------
extern "C" void kernel_launch(void* const* d_in, const int* in_sizes, int n_in,
                              void* d_out, int out_size) {
    const float* x      = (const float*)d_in[0];
    const int*   ei     = (const int*)d_in[1];
    const int*   batch  = (const int*)d_in[2];
    const float* W1_0   = (const float*)d_in[3];
    const float* bn_g_0 = (const float*)d_in[4];
    const float* bn_b_0 = (const float*)d_in[5];
    const float* bn_m_0 = (const float*)d_in[6];
    const float* bn_v_0 = (const float*)d_in[7];
    const float* W2_0   = (const float*)d_in[8];
    const float* W1_r   = (const float*)d_in[9];
    const float* bn_g_r = (const float*)d_in[10];
    const float* bn_b_r = (const float*)d_in[11];
    const float* bn_m_r = (const float*)d_in[12];
    const float* bn_v_r = (const float*)d_in[13];
    const float* W2_r   = (const float*)d_in[14];
    const float* lin1   = (const float*)d_in[15];
    const float* lin2   = (const float*)d_in[16];
    const float* lin2b  = (const float*)d_in[17];
    float* out = (float*)d_out;

    const int TPB = 256;
    int gridEdges = (N_EDGES + TPB - 1) / TPB;
    int gridGemm0 = (N_NODES + 255) / 256;             // 391
    int gridDual = (N_NODES + 127) / 128;              // 782
    int gridAgg = ((N_NODES / 2) * 32 + TPB - 1) / TPB;  // 2 nodes per warp -> 6250

    cudaStream_t side;
    cudaStreamCreateWithFlags(&side, cudaStreamNonBlocking);
    cudaEvent_t evFork, evJoin;
    cudaEventCreateWithFlags(&evFork, cudaEventDisableTiming);
    cudaEventCreateWithFlags(&evJoin, cudaEventDisableTiming);

    cudaEventRecord(evFork, 0);
    cudaStreamWaitEvent(side, evFork, 0);
    k_gemm0<<<gridGemm0, TPB, 0, side>>>(x, W1_0);     // y0 = x @ W1_0
    cudaEventRecord(evJoin, side);

    k_count<<<gridEdges, TPB>>>(ei, batch);
    k_scan1<<<SCAN_BLK, 1024>>>();
    k_scan23<<<SCAN_BLK, 1024>>>();
    k_scatter<<<gridEdges, TPB>>>(ei);

    cudaStreamWaitEvent(0, evJoin, 0);

    k_agg<<<gridAgg, TPB>>>(bn_g_0, bn_b_0, bn_m_0, bn_v_0);
    k_dual<true><<<gridDual, 128>>>(W2_0, W1_r + 0 * 4096, nullptr);
    k_agg<<<gridAgg, TPB>>>(bn_g_r + 0, bn_b_r + 0, bn_m_r + 0, bn_v_r + 0);
    k_dual<true><<<gridDual, 128>>>(W2_r + 0 * 4096, W1_r + 1 * 4096, nullptr);
    k_agg<<<gridAgg, TPB>>>(bn_g_r + 64, bn_b_r + 64, bn_m_r + 64, bn_v_r + 64);
    k_dual<true><<<gridDual, 128>>>(W2_r + 1 * 4096, W1_r + 2 * 4096, nullptr);
    k_agg<<<gridAgg, TPB>>>(bn_g_r + 128, bn_b_r + 128, bn_m_r + 128, bn_v_r + 128);
    k_dual<false><<<gridDual, 128>>>(W2_r + 2 * 4096, nullptr, batch);

    k_final<<<1, 128>>>(lin1, lin2, lin2b, out);

    cudaStreamDestroy(side);
    cudaEventDestroy(evFork);
    cudaEventDestroy(evJoin);
}

// round 11
// speedup vs baseline: 2.0935x; 1.0134x over previous
#include <cuda_runtime.h>
#include <cuda_fp16.h>
#include <math.h>

#define N_NODES 100000
#define N_EDGES 1000000
#define N_GRAPHS 128
#define HD 64
#define BN_EPS 1e-5f

#define SCAN_BLK 25            // ceil(100000 / 4096)

// ---------------- scratch (device globals; no allocation allowed) ----------------
// Self-cleaning invariant: every buffer that must start at zero is re-zeroed by
// the kernel that consumes it.
__device__ __align__(16) int    g_rowptr[N_NODES + 1];
__device__ __align__(16) int    g_cursor[N_NODES];
__device__ __align__(16) int    g_deg[N_NODES];
__device__ __align__(16) int    g_bsum[SCAN_BLK];
__device__ __align__(16) int    g_csrsrc[N_EDGES];
__device__ __align__(16) __half g_y[N_NODES * HD];
__device__ __align__(16) __half g_a[N_NODES * HD];
__device__ __align__(16) float  g_pool[N_GRAPHS * HD];
__device__ __align__(16) int    g_cnt[N_GRAPHS];

// ---------------- helpers ----------------
__device__ __forceinline__ unsigned f2tf(float f) {
    unsigned u;
    asm("cvt.rna.tf32.f32 %0, %1;" : "=r"(u) : "f"(f));
    return u;
}
__device__ __forceinline__ void mma_tf32(float* c, const unsigned* a,
                                         unsigned b0, unsigned b1) {
    asm("mma.sync.aligned.m16n8k8.row.col.f32.tf32.tf32.f32 "
        "{%0,%1,%2,%3},{%4,%5,%6,%7},{%8,%9},{%0,%1,%2,%3};"
        : "+f"(c[0]), "+f"(c[1]), "+f"(c[2]), "+f"(c[3])
        : "r"(a[0]), "r"(a[1]), "r"(a[2]), "r"(a[3]), "r"(b0), "r"(b1));
}

// ---------------- CSR build ----------------
__global__ void k_count(const int* __restrict__ ei,
                        const int* __restrict__ batch) {
    int e = blockIdx.x * blockDim.x + threadIdx.x;
    if (e < N_EDGES) atomicAdd(&g_deg[ei[N_EDGES + e]], 1);
    if (e < N_NODES) atomicAdd(&g_cnt[batch[e]], 1);
}

__global__ __launch_bounds__(1024) void k_scan1() {
    __shared__ int warpsum[32];
    int tid = threadIdx.x, lane = tid & 31, wid = tid >> 5;
    int i0 = blockIdx.x * 4096 + tid * 4;
    int4 v = make_int4(0, 0, 0, 0);
    if (i0 + 3 < N_NODES) {
        v = *(const int4*)&g_deg[i0];
    } else {
        if (i0 + 0 < N_NODES) v.x = g_deg[i0 + 0];
        if (i0 + 1 < N_NODES) v.y = g_deg[i0 + 1];
        if (i0 + 2 < N_NODES) v.z = g_deg[i0 + 2];
        if (i0 + 3 < N_NODES) v.w = g_deg[i0 + 3];
    }
    int s = v.x + v.y + v.z + v.w;
    int x = s;
    #pragma unroll
    for (int off = 1; off < 32; off <<= 1) {
        int t = __shfl_up_sync(0xffffffffu, x, off);
        if (lane >= off) x += t;
    }
    if (lane == 31) warpsum[wid] = x;
    __syncthreads();
    if (wid == 0) {
        int w = warpsum[lane];
        #pragma unroll
        for (int off = 1; off < 32; off <<= 1) {
            int t = __shfl_up_sync(0xffffffffu, w, off);
            if (lane >= off) w += t;
        }
        warpsum[lane] = w;
    }
    __syncthreads();
    int woff = (wid > 0) ? warpsum[wid - 1] : 0;
    int excl = woff + (x - s);
    int p0 = excl + v.x, p1 = p0 + v.y, p2 = p1 + v.z;
    if (i0 + 0 < N_NODES) g_cursor[i0 + 0] = excl;
    if (i0 + 1 < N_NODES) g_cursor[i0 + 1] = p0;
    if (i0 + 2 < N_NODES) g_cursor[i0 + 2] = p1;
    if (i0 + 3 < N_NODES) g_cursor[i0 + 3] = p2;
    if (tid == 1023) g_bsum[blockIdx.x] = warpsum[31];
}

__global__ __launch_bounds__(1024) void k_scan23() {
    __shared__ int s_off;
    int tid = threadIdx.x;
    if (tid < 32) {
        int lane = tid;
        int v = (lane < SCAN_BLK) ? g_bsum[lane] : 0;
        int x = v;
        #pragma unroll
        for (int off = 1; off < 32; off <<= 1) {
            int t = __shfl_up_sync(0xffffffffu, x, off);
            if (lane >= off) x += t;
        }
        if (lane == blockIdx.x) s_off = x - v;
    }
    __syncthreads();
    int off = s_off;
    int i0 = blockIdx.x * 4096 + tid * 4;
    if (i0 + 3 < N_NODES) {
        int4 c = *(const int4*)&g_cursor[i0];
        c.x += off; c.y += off; c.z += off; c.w += off;
        *(int4*)&g_cursor[i0] = c;
        *(int4*)&g_rowptr[i0] = c;
        *(int4*)&g_deg[i0] = make_int4(0, 0, 0, 0);
    } else {
        #pragma unroll
        for (int j = 0; j < 4; j++) {
            if (i0 + j < N_NODES) {
                int c = g_cursor[i0 + j] + off;
                g_cursor[i0 + j] = c;
                g_rowptr[i0 + j] = c;
                g_deg[i0 + j] = 0;
            }
        }
    }
    if (blockIdx.x == 0 && tid == 0) g_rowptr[N_NODES] = N_EDGES;
}

__global__ void k_scatter(const int* __restrict__ ei) {
    int e = blockIdx.x * blockDim.x + threadIdx.x;
    if (e >= N_EDGES) return;
    int d = ei[N_EDGES + e];
    int s = ei[e];
    int p = atomicAdd(&g_cursor[d], 1);
    g_csrsrc[p] = s;
}

// ---------------- layer-0 input GEMM: g_y = x[N,128] @ W1_0[128,64] (TF32) ----
__global__ __launch_bounds__(256) void k_gemm0(const float* __restrict__ A,
                                               const float* __restrict__ W) {
    constexpr int K = 128;
    __shared__ unsigned sA[256 * 17];
    __shared__ unsigned sW[16 * 65];
    int tid = threadIdx.x;
    int wid = tid >> 5, lane = tid & 31;
    int tg = lane >> 2, tig = lane & 3;
    int row0 = blockIdx.x * 256;

    float c[2][8][4];
    #pragma unroll
    for (int mt = 0; mt < 2; mt++)
        #pragma unroll
        for (int nt = 0; nt < 8; nt++)
            #pragma unroll
            for (int j = 0; j < 4; j++) c[mt][nt][j] = 0.f;

    for (int ch = 0; ch < 8; ch++) {
        int kbase = ch * 16;
        #pragma unroll
        for (int i = 0; i < 4; i++) {
            int idx = tid + i * 256;
            int r = idx >> 2, c4 = idx & 3;
            int grow = row0 + r;
            float4 v = make_float4(0.f, 0.f, 0.f, 0.f);
            if (grow < N_NODES)
                v = *(const float4*)(A + (size_t)grow * K + kbase + c4 * 4);
            unsigned* p = &sA[r * 17 + c4 * 4];
            p[0] = f2tf(v.x); p[1] = f2tf(v.y); p[2] = f2tf(v.z); p[3] = f2tf(v.w);
        }
        {
            int k = tid >> 4, c4 = tid & 15;
            float4 v = *(const float4*)(W + (size_t)(kbase + k) * 64 + c4 * 4);
            unsigned* p = &sW[k * 65 + c4 * 4];
            p[0] = f2tf(v.x); p[1] = f2tf(v.y); p[2] = f2tf(v.z); p[3] = f2tf(v.w);
        }
        __syncthreads();
        #pragma unroll
        for (int ks = 0; ks < 2; ks++) {
            int ko = ks * 8;
            unsigned a[2][4];
            #pragma unroll
            for (int mt = 0; mt < 2; mt++) {
                int rr = wid * 32 + mt * 16 + tg;
                a[mt][0] = sA[rr * 17 + ko + tig];
                a[mt][1] = sA[(rr + 8) * 17 + ko + tig];
                a[mt][2] = sA[rr * 17 + ko + tig + 4];
                a[mt][3] = sA[(rr + 8) * 17 + ko + tig + 4];
            }
            #pragma unroll
            for (int nt = 0; nt < 8; nt++) {
                unsigned b0 = sW[(ko + tig) * 65 + nt * 8 + tg];
                unsigned b1 = sW[(ko + tig + 4) * 65 + nt * 8 + tg];
                mma_tf32(c[0][nt], a[0], b0, b1);
                mma_tf32(c[1][nt], a[1], b0, b1);
            }
        }
        __syncthreads();
    }
    #pragma unroll
    for (int mt = 0; mt < 2; mt++) {
        int row = row0 + wid * 32 + mt * 16 + tg;
        #pragma unroll
        for (int half_i = 0; half_i < 2; half_i++) {
            int r = row + half_i * 8;
            if (r < N_NODES) {
                #pragma unroll
                for (int nt = 0; nt < 8; nt++) {
                    int col = nt * 8 + tig * 2;
                    *(__half2*)(g_y + (size_t)r * HD + col) =
                        __float22half2_rn(make_float2(c[mt][nt][half_i * 2 + 0],
                                                      c[mt][nt][half_i * 2 + 1]));
                }
            }
        }
    }
}

// ---------------- chained dual GEMM (unchanged) ----------------
template <bool DUAL>
__global__ __launch_bounds__(128) void k_dual(const float* __restrict__ W2,
                                              const float* __restrict__ W1n,
                                              const int* __restrict__ batch) {
    __shared__ unsigned sA[128 * 68];
    __shared__ unsigned sW[16 * 68];

    int tid = threadIdx.x, wid = tid >> 5, lane = tid & 31;
    int tg = lane >> 2, tig = lane & 3;
    int row0 = blockIdx.x * 128;

    #pragma unroll
    for (int i = 0; i < 8; i++) {
        int idx = tid + i * 128;
        int r = idx >> 3, seg = idx & 7;
        int grow = row0 + r;
        uint4 raw = make_uint4(0u, 0u, 0u, 0u);
        if (grow < N_NODES)
            raw = *(const uint4*)(g_a + (size_t)grow * HD + seg * 8);
        unsigned* p = &sA[r * 68 + seg * 8];
        float2 f;
        f = __half22float2(*(__half2*)&raw.x); p[0] = f2tf(f.x); p[1] = f2tf(f.y);
        f = __half22float2(*(__half2*)&raw.y); p[2] = f2tf(f.x); p[3] = f2tf(f.y);
        f = __half22float2(*(__half2*)&raw.z); p[4] = f2tf(f.x); p[5] = f2tf(f.y);
        f = __half22float2(*(__half2*)&raw.w); p[6] = f2tf(f.x); p[7] = f2tf(f.y);
    }

    float c[2][8][4];
    #pragma unroll
    for (int mt = 0; mt < 2; mt++)
        #pragma unroll
        for (int nt = 0; nt < 8; nt++)
            #pragma unroll
            for (int j = 0; j < 4; j++) c[mt][nt][j] = 0.f;

    for (int ch = 0; ch < 4; ch++) {
        __syncthreads();
        #pragma unroll
        for (int it = 0; it < 2; it++) {
            int id = tid + it * 128;
            int k = id >> 4, c4 = id & 15;
            float4 v = *(const float4*)(W2 + (size_t)(ch * 16 + k) * 64 + c4 * 4);
            unsigned* p = &sW[k * 68 + c4 * 4];
            p[0] = f2tf(v.x); p[1] = f2tf(v.y); p[2] = f2tf(v.z); p[3] = f2tf(v.w);
        }
        __syncthreads();
        #pragma unroll
        for (int ks = 0; ks < 2; ks++) {
            int ko = ks * 8;
            int kg = ch * 16 + ko;
            unsigned a[2][4];
            #pragma unroll
            for (int mt = 0; mt < 2; mt++) {
                int rr = wid * 32 + mt * 16 + tg;
                a[mt][0] = sA[rr * 68 + kg + tig];
                a[mt][1] = sA[(rr + 8) * 68 + kg + tig];
                a[mt][2] = sA[rr * 68 + kg + tig + 4];
                a[mt][3] = sA[(rr + 8) * 68 + kg + tig + 4];
            }
            #pragma unroll
            for (int nt = 0; nt < 8; nt++) {
                unsigned b0 = sW[(ko + tig) * 68 + nt * 8 + tg];
                unsigned b1 = sW[(ko + tig + 4) * 68 + nt * 8 + tg];
                mma_tf32(c[0][nt], a[0], b0, b1);
                mma_tf32(c[1][nt], a[1], b0, b1);
            }
        }
    }

    if (!DUAL) {
        #pragma unroll
        for (int mt = 0; mt < 2; mt++) {
            int row = row0 + wid * 32 + mt * 16 + tg;
            #pragma unroll
            for (int half_i = 0; half_i < 2; half_i++) {
                int r = row + half_i * 8;
                if (r < N_NODES) {
                    int b = batch[r];
                    #pragma unroll
                    for (int nt = 0; nt < 8; nt++) {
                        int col = nt * 8 + tig * 2;
                        atomicAdd(&g_pool[b * HD + col],
                                  fmaxf(c[mt][nt][half_i * 2 + 0], 0.f));
                        atomicAdd(&g_pool[b * HD + col + 1],
                                  fmaxf(c[mt][nt][half_i * 2 + 1], 0.f));
                    }
                }
            }
        }
        return;
    }

    #pragma unroll
    for (int mt = 0; mt < 2; mt++) {
        int rlo = wid * 32 + mt * 16 + tg;
        #pragma unroll
        for (int nt = 0; nt < 8; nt++) {
            int col = nt * 8 + 2 * tig;
            uint2 lo, hi;
            lo.x = f2tf(fmaxf(c[mt][nt][0], 0.f));
            lo.y = f2tf(fmaxf(c[mt][nt][1], 0.f));
            hi.x = f2tf(fmaxf(c[mt][nt][2], 0.f));
            hi.y = f2tf(fmaxf(c[mt][nt][3], 0.f));
            *(uint2*)&sA[rlo * 68 + col] = lo;
            *(uint2*)&sA[(rlo + 8) * 68 + col] = hi;
        }
    }
    __syncwarp();
    #pragma unroll
    for (int mt = 0; mt < 2; mt++)
        #pragma unroll
        for (int nt = 0; nt < 8; nt++)
            #pragma unroll
            for (int j = 0; j < 4; j++) c[mt][nt][j] = 0.f;

    for (int ch = 0; ch < 4; ch++) {
        __syncthreads();
        #pragma unroll
        for (int it = 0; it < 2; it++) {
            int id = tid + it * 128;
            int k = id >> 4, c4 = id & 15;
            float4 v = *(const float4*)(W1n + (size_t)(ch * 16 + k) * 64 + c4 * 4);
            unsigned* p = &sW[k * 68 + c4 * 4];
            p[0] = f2tf(v.x); p[1] = f2tf(v.y); p[2] = f2tf(v.z); p[3] = f2tf(v.w);
        }
        __syncthreads();
        #pragma unroll
        for (int ks = 0; ks < 2; ks++) {
            int ko = ks * 8;
            int kg = ch * 16 + ko;
            unsigned a[2][4];
            #pragma unroll
            for (int mt = 0; mt < 2; mt++) {
                int rr = wid * 32 + mt * 16 + tg;
                a[mt][0] = sA[rr * 68 + kg + tig];
                a[mt][1] = sA[(rr + 8) * 68 + kg + tig];
                a[mt][2] = sA[rr * 68 + kg + tig + 4];
                a[mt][3] = sA[(rr + 8) * 68 + kg + tig + 4];
            }
            #pragma unroll
            for (int nt = 0; nt < 8; nt++) {
                unsigned b0 = sW[(ko + tig) * 68 + nt * 8 + tg];
                unsigned b1 = sW[(ko + tig + 4) * 68 + nt * 8 + tg];
                mma_tf32(c[0][nt], a[0], b0, b1);
                mma_tf32(c[1][nt], a[1], b0, b1);
            }
        }
    }

    #pragma unroll
    for (int mt = 0; mt < 2; mt++) {
        int row = row0 + wid * 32 + mt * 16 + tg;
        #pragma unroll
        for (int half_i = 0; half_i < 2; half_i++) {
            int r = row + half_i * 8;
            if (r < N_NODES) {
                #pragma unroll
                for (int nt = 0; nt < 8; nt++) {
                    int col = nt * 8 + tig * 2;
                    *(__half2*)(g_y + (size_t)r * HD + col) =
                        __float22half2_rn(make_float2(c[mt][nt][half_i * 2 + 0],
                                                      c[mt][nt][half_i * 2 + 1]));
                }
            }
        }
    }
}

// ---------------- aggregation + BN + relu: FOUR nodes per warp ----------------
// lane groups of 8: group q serves node 4w+q; each lane loads uint4 (8 halves),
// 8 lanes cover the 128B row. Four independent gather chains per warp -> 4x MLP.
__global__ __launch_bounds__(256) void k_agg(const float* __restrict__ gam,
                                             const float* __restrict__ bet,
                                             const float* __restrict__ mea,
                                             const float* __restrict__ var) {
    __shared__ float sScale[64], sShift[64];
    int tid = threadIdx.x;
    if (tid < 64) {
        float sc = rsqrtf(var[tid] + BN_EPS) * gam[tid];
        sScale[tid] = sc;
        sShift[tid] = bet[tid] - mea[tid] * sc;
    }
    __syncthreads();

    int gw = (blockIdx.x * 256 + tid) >> 5;
    if (gw >= N_NODES / 4) return;
    int lane = tid & 31;
    int q = lane >> 3;         // node group 0..3
    int sub = lane & 7;        // 8-half segment within the row
    int node = 4 * gw + q;

    const uint4* yv = (const uint4*)g_y;   // 8 uint4 per 64-half row

    // self row
    float a[8];
    {
        uint4 raw = yv[(size_t)node * 8 + sub];
        float2 f0 = __half22float2(*(__half2*)&raw.x);
        float2 f1 = __half22float2(*(__half2*)&raw.y);
        float2 f2 = __half22float2(*(__half2*)&raw.z);
        float2 f3 = __half22float2(*(__half2*)&raw.w);
        a[0] = f0.x; a[1] = f0.y; a[2] = f1.x; a[3] = f1.y;
        a[4] = f2.x; a[5] = f2.y; a[6] = f3.x; a[7] = f3.y;
    }

    int b = g_rowptr[node];
    int end = g_rowptr[node + 1];

    while (__any_sync(0xffffffffu, b < end)) {
        int n = end - b;
        if (n > 8) n = 8;
        if (n < 0) n = 0;
        int idx = (sub < n) ? g_csrsrc[b + sub] : 0;
        // warp-max batch size across the 4 groups
        int m = n;
        m = max(m, __shfl_xor_sync(0xffffffffu, m, 8));
        m = max(m, __shfl_xor_sync(0xffffffffu, m, 16));
        int srcbase = q * 8;
        int t = 0;
        for (; t + 4 <= m; t += 4) {
            int s0 = __shfl_sync(0xffffffffu, idx, srcbase + t + 0);
            int s1 = __shfl_sync(0xffffffffu, idx, srcbase + t + 1);
            int s2 = __shfl_sync(0xffffffffu, idx, srcbase + t + 2);
            int s3 = __shfl_sync(0xffffffffu, idx, srcbase + t + 3);
            uint4 r0 = yv[(size_t)s0 * 8 + sub];
            uint4 r1 = yv[(size_t)s1 * 8 + sub];
            uint4 r2 = yv[(size_t)s2 * 8 + sub];
            uint4 r3 = yv[(size_t)s3 * 8 + sub];
            if (t + 0 < n) {
                float2 u0 = __half22float2(*(__half2*)&r0.x);
                float2 u1 = __half22float2(*(__half2*)&r0.y);
                float2 u2 = __half22float2(*(__half2*)&r0.z);
                float2 u3 = __half22float2(*(__half2*)&r0.w);
                a[0] += u0.x; a[1] += u0.y; a[2] += u1.x; a[3] += u1.y;
                a[4] += u2.x; a[5] += u2.y; a[6] += u3.x; a[7] += u3.y;
            }
            if (t + 1 < n) {
                float2 u0 = __half22float2(*(__half2*)&r1.x);
                float2 u1 = __half22float2(*(__half2*)&r1.y);
                float2 u2 = __half22float2(*(__half2*)&r1.z);
                float2 u3 = __half22float2(*(__half2*)&r1.w);
                a[0] += u0.x; a[1] += u0.y; a[2] += u1.x; a[3] += u1.y;
                a[4] += u2.x; a[5] += u2.y; a[6] += u3.x; a[7] += u3.y;
            }
            if (t + 2 < n) {
                float2 u0 = __half22float2(*(__half2*)&r2.x);
                float2 u1 = __half22float2(*(__half2*)&r2.y);
                float2 u2 = __half22float2(*(__half2*)&r2.z);
                float2 u3 = __half22float2(*(__half2*)&r2.w);
                a[0] += u0.x; a[1] += u0.y; a[2] += u1.x; a[3] += u1.y;
                a[4] += u2.x; a[5] += u2.y; a[6] += u3.x; a[7] += u3.y;
            }
            if (t + 3 < n) {
                float2 u0 = __half22float2(*(__half2*)&r3.x);
                float2 u1 = __half22float2(*(__half2*)&r3.y);
                float2 u2 = __half22float2(*(__half2*)&r3.z);
                float2 u3 = __half22float2(*(__half2*)&r3.w);
                a[0] += u0.x; a[1] += u0.y; a[2] += u1.x; a[3] += u1.y;
                a[4] += u2.x; a[5] += u2.y; a[6] += u3.x; a[7] += u3.y;
            }
        }
        for (; t < m; t++) {
            int s = __shfl_sync(0xffffffffu, idx, srcbase + t);
            uint4 r = yv[(size_t)s * 8 + sub];
            if (t < n) {
                float2 u0 = __half22float2(*(__half2*)&r.x);
                float2 u1 = __half22float2(*(__half2*)&r.y);
                float2 u2 = __half22float2(*(__half2*)&r.z);
                float2 u3 = __half22float2(*(__half2*)&r.w);
                a[0] += u0.x; a[1] += u0.y; a[2] += u1.x; a[3] += u1.y;
                a[4] += u2.x; a[5] += u2.y; a[6] += u3.x; a[7] += u3.y;
            }
        }
        b += 8;
    }

    // BN + relu on 8 columns
    int c0 = sub * 8;
    float4 scA = *(float4*)&sScale[c0];
    float4 scB = *(float4*)&sScale[c0 + 4];
    float4 shA = *(float4*)&sShift[c0];
    float4 shB = *(float4*)&sShift[c0 + 4];
    float h0 = fmaxf(fmaf(a[0], scA.x, shA.x), 0.f);
    float h1 = fmaxf(fmaf(a[1], scA.y, shA.y), 0.f);
    float h2 = fmaxf(fmaf(a[2], scA.z, shA.z), 0.f);
    float h3 = fmaxf(fmaf(a[3], scA.w, shA.w), 0.f);
    float h4 = fmaxf(fmaf(a[4], scB.x, shB.x), 0.f);
    float h5 = fmaxf(fmaf(a[5], scB.y, shB.y), 0.f);
    float h6 = fmaxf(fmaf(a[6], scB.z, shB.z), 0.f);
    float h7 = fmaxf(fmaf(a[7], scB.w, shB.w), 0.f);
    uint4 outv;
    *(__half2*)&outv.x = __float22half2_rn(make_float2(h0, h1));
    *(__half2*)&outv.y = __float22half2_rn(make_float2(h2, h3));
    *(__half2*)&outv.z = __float22half2_rn(make_float2(h4, h5));
    *(__half2*)&outv.w = __float22half2_rn(make_float2(h6, h7));
    ((uint4*)g_a)[(size_t)node * 8 + sub] = outv;
}

// ---------------- final head (self-cleans g_pool / g_cnt) ----------------
__global__ void k_final(const float* __restrict__ lin1, const float* __restrict__ lin2,
                        const float* __restrict__ lb, float* __restrict__ out) {
    __shared__ float sL1[64 * 64];
    __shared__ float sL2[64 * 10];
    __shared__ float sB[10];
    int tid = threadIdx.x;
    for (int i = tid; i < 64 * 64; i += 128) sL1[i] = lin1[i];
    for (int i = tid; i < 64 * 10; i += 128) sL2[i] = lin2[i];
    if (tid < 10) sB[tid] = lb[tid];
    __syncthreads();
    if (tid < N_GRAPHS) {
        float cnt = (float)g_cnt[tid];
        if (cnt < 1.f) cnt = 1.f;
        float pooled[64];
        #pragma unroll
        for (int k = 0; k < 64; k++) {
            pooled[k] = g_pool[tid * 64 + k] / cnt;
            g_pool[tid * 64 + k] = 0.f;
        }
        g_cnt[tid] = 0;
        float o[10];
        #pragma unroll
        for (int c = 0; c < 10; c++) o[c] = sB[c];
        for (int j = 0; j < 64; j++) {
            float z = 0.f;
            #pragma unroll
            for (int k = 0; k < 64; k++) z += pooled[k] * sL1[k * 64 + j];
            z = fmaxf(z, 0.f);
            #pragma unroll
            for (int c = 0; c < 10; c++) o[c] += z * sL2[j * 10 + c];
        }
        float mx = o[0];
        #pragma unroll
        for (int c = 1; c < 10; c++) mx = fmaxf(mx, o[c]);
        float se = 0.f;
        #pragma unroll
        for (int c = 0; c < 10; c++) se += expf(o[c] - mx);
        float lse = logf(se) + mx;
        #pragma unroll
        for (int c = 0; c < 10; c++) out[tid * 10 + c] = o[c] - lse;
    }
}

// ---------------- launch ----------------
extern "C" void kernel_launch(void* const* d_in, const int* in_sizes, int n_in,
                              void* d_out, int out_size) {
    const float* x      = (const float*)d_in[0];
    const int*   ei     = (const int*)d_in[1];
    const int*   batch  = (const int*)d_in[2];
    const float* W1_0   = (const float*)d_in[3];
    const float* bn_g_0 = (const float*)d_in[4];
    const float* bn_b_0 = (const float*)d_in[5];
    const float* bn_m_0 = (const float*)d_in[6];
    const float* bn_v_0 = (const float*)d_in[7];
    const float* W2_0   = (const float*)d_in[8];
    const float* W1_r   = (const float*)d_in[9];
    const float* bn_g_r = (const float*)d_in[10];
    const float* bn_b_r = (const float*)d_in[11];
    const float* bn_m_r = (const float*)d_in[12];
    const float* bn_v_r = (const float*)d_in[13];
    const float* W2_r   = (const float*)d_in[14];
    const float* lin1   = (const float*)d_in[15];
    const float* lin2   = (const float*)d_in[16];
    const float* lin2b  = (const float*)d_in[17];
    float* out = (float*)d_out;

    const int TPB = 256;
    int gridEdges = (N_EDGES + TPB - 1) / TPB;
    int gridGemm0 = (N_NODES + 255) / 256;               // 391
    int gridDual = (N_NODES + 127) / 128;                // 782
    int gridAgg = ((N_NODES / 4) * 32 + TPB - 1) / TPB;  // 4 nodes/warp -> 3125

    cudaStream_t side;
    cudaStreamCreateWithFlags(&side, cudaStreamNonBlocking);
    cudaEvent_t evFork, evJoin;
    cudaEventCreateWithFlags(&evFork, cudaEventDisableTiming);
    cudaEventCreateWithFlags(&evJoin, cudaEventDisableTiming);

    cudaEventRecord(evFork, 0);
    cudaStreamWaitEvent(side, evFork, 0);
    k_gemm0<<<gridGemm0, TPB, 0, side>>>(x, W1_0);     // y0 = x @ W1_0
    cudaEventRecord(evJoin, side);

    k_count<<<gridEdges, TPB>>>(ei, batch);
    k_scan1<<<SCAN_BLK, 1024>>>();
    k_scan23<<<SCAN_BLK, 1024>>>();
    k_scatter<<<gridEdges, TPB>>>(ei);

    cudaStreamWaitEvent(0, evJoin, 0);

    k_agg<<<gridAgg, TPB>>>(bn_g_0, bn_b_0, bn_m_0, bn_v_0);
    k_dual<true><<<gridDual, 128>>>(W2_0, W1_r + 0 * 4096, nullptr);
    k_agg<<<gridAgg, TPB>>>(bn_g_r + 0, bn_b_r + 0, bn_m_r + 0, bn_v_r + 0);
    k_dual<true><<<gridDual, 128>>>(W2_r + 0 * 4096, W1_r + 1 * 4096, nullptr);
    k_agg<<<gridAgg, TPB>>>(bn_g_r + 64, bn_b_r + 64, bn_m_r + 64, bn_v_r + 64);
    k_dual<true><<<gridDual, 128>>>(W2_r + 1 * 4096, W1_r + 2 * 4096, nullptr);
    k_agg<<<gridAgg, TPB>>>(bn_g_r + 128, bn_b_r + 128, bn_m_r + 128, bn_v_r + 128);
    k_dual<false><<<gridDual, 128>>>(W2_r + 2 * 4096, nullptr, batch);

    k_final<<<1, 128>>>(lin1, lin2, lin2b, out);

    cudaStreamDestroy(side);
    cudaEventDestroy(evFork);
    cudaEventDestroy(evJoin);
}

// round 12
// speedup vs baseline: 2.3106x; 1.1037x over previous
#include <cuda_runtime.h>
#include <cuda_fp16.h>
#include <math.h>

#define N_NODES 100000
#define N_EDGES 1000000
#define N_GRAPHS 128
#define HD 64
#define BN_EPS 1e-5f

#define SCAN_BLK 25            // ceil(100000 / 4096)

// ---------------- scratch (device globals; no allocation allowed) ----------------
__device__ __align__(16) int    g_rowptr[N_NODES + 1];
__device__ __align__(16) int    g_cursor[N_NODES];
__device__ __align__(16) int    g_deg[N_NODES];
__device__ __align__(16) int    g_bsum[SCAN_BLK];
__device__ __align__(16) int    g_csrsrc[N_EDGES];
__device__ __align__(16) __half g_y[N_NODES * HD];
__device__ __align__(16) __half g_a[N_NODES * HD];
__device__ __align__(16) float  g_pool[N_GRAPHS * HD];
__device__ __align__(16) int    g_cnt[N_GRAPHS];

// ---------------- helpers ----------------
__device__ __forceinline__ unsigned f2tf(float f) {
    unsigned u;
    asm("cvt.rna.tf32.f32 %0, %1;" : "=r"(u) : "f"(f));
    return u;
}
__device__ __forceinline__ void mma_tf32(float* c, const unsigned* a,
                                         unsigned b0, unsigned b1) {
    asm("mma.sync.aligned.m16n8k8.row.col.f32.tf32.tf32.f32 "
        "{%0,%1,%2,%3},{%4,%5,%6,%7},{%8,%9},{%0,%1,%2,%3};"
        : "+f"(c[0]), "+f"(c[1]), "+f"(c[2]), "+f"(c[3])
        : "r"(a[0]), "r"(a[1]), "r"(a[2]), "r"(a[3]), "r"(b0), "r"(b1));
}
// fp16 MMA, fp32 accumulate: m16n8k16
__device__ __forceinline__ void mma_f16(float* c, const unsigned* a,
                                        unsigned b0, unsigned b1) {
    asm("mma.sync.aligned.m16n8k16.row.col.f32.f16.f16.f32 "
        "{%0,%1,%2,%3},{%4,%5,%6,%7},{%8,%9},{%0,%1,%2,%3};"
        : "+f"(c[0]), "+f"(c[1]), "+f"(c[2]), "+f"(c[3])
        : "r"(a[0]), "r"(a[1]), "r"(a[2]), "r"(a[3]), "r"(b0), "r"(b1));
}

// ---------------- CSR build ----------------
// 4 edges per thread: int4 loads, 4 independent atomics -> 4x MLP
__global__ void k_count(const int* __restrict__ ei,
                        const int* __restrict__ batch) {
    int e = (blockIdx.x * blockDim.x + threadIdx.x) * 4;
    if (e < N_EDGES) {
        int4 d = *(const int4*)&ei[N_EDGES + e];
        atomicAdd(&g_deg[d.x], 1);
        atomicAdd(&g_deg[d.y], 1);
        atomicAdd(&g_deg[d.z], 1);
        atomicAdd(&g_deg[d.w], 1);
    }
    if (e < N_NODES) {
        int4 b = *(const int4*)&batch[e];
        atomicAdd(&g_cnt[b.x], 1);
        atomicAdd(&g_cnt[b.y], 1);
        atomicAdd(&g_cnt[b.z], 1);
        atomicAdd(&g_cnt[b.w], 1);
    }
}

__global__ __launch_bounds__(1024) void k_scan1() {
    __shared__ int warpsum[32];
    int tid = threadIdx.x, lane = tid & 31, wid = tid >> 5;
    int i0 = blockIdx.x * 4096 + tid * 4;
    int4 v = make_int4(0, 0, 0, 0);
    if (i0 + 3 < N_NODES) {
        v = *(const int4*)&g_deg[i0];
    } else {
        if (i0 + 0 < N_NODES) v.x = g_deg[i0 + 0];
        if (i0 + 1 < N_NODES) v.y = g_deg[i0 + 1];
        if (i0 + 2 < N_NODES) v.z = g_deg[i0 + 2];
        if (i0 + 3 < N_NODES) v.w = g_deg[i0 + 3];
    }
    int s = v.x + v.y + v.z + v.w;
    int x = s;
    #pragma unroll
    for (int off = 1; off < 32; off <<= 1) {
        int t = __shfl_up_sync(0xffffffffu, x, off);
        if (lane >= off) x += t;
    }
    if (lane == 31) warpsum[wid] = x;
    __syncthreads();
    if (wid == 0) {
        int w = warpsum[lane];
        #pragma unroll
        for (int off = 1; off < 32; off <<= 1) {
            int t = __shfl_up_sync(0xffffffffu, w, off);
            if (lane >= off) w += t;
        }
        warpsum[lane] = w;
    }
    __syncthreads();
    int woff = (wid > 0) ? warpsum[wid - 1] : 0;
    int excl = woff + (x - s);
    int p0 = excl + v.x, p1 = p0 + v.y, p2 = p1 + v.z;
    if (i0 + 0 < N_NODES) g_cursor[i0 + 0] = excl;
    if (i0 + 1 < N_NODES) g_cursor[i0 + 1] = p0;
    if (i0 + 2 < N_NODES) g_cursor[i0 + 2] = p1;
    if (i0 + 3 < N_NODES) g_cursor[i0 + 3] = p2;
    if (tid == 1023) g_bsum[blockIdx.x] = warpsum[31];
}

__global__ __launch_bounds__(1024) void k_scan23() {
    __shared__ int s_off;
    int tid = threadIdx.x;
    if (tid < 32) {
        int lane = tid;
        int v = (lane < SCAN_BLK) ? g_bsum[lane] : 0;
        int x = v;
        #pragma unroll
        for (int off = 1; off < 32; off <<= 1) {
            int t = __shfl_up_sync(0xffffffffu, x, off);
            if (lane >= off) x += t;
        }
        if (lane == blockIdx.x) s_off = x - v;
    }
    __syncthreads();
    int off = s_off;
    int i0 = blockIdx.x * 4096 + tid * 4;
    if (i0 + 3 < N_NODES) {
        int4 c = *(const int4*)&g_cursor[i0];
        c.x += off; c.y += off; c.z += off; c.w += off;
        *(int4*)&g_cursor[i0] = c;
        *(int4*)&g_rowptr[i0] = c;
        *(int4*)&g_deg[i0] = make_int4(0, 0, 0, 0);
    } else {
        #pragma unroll
        for (int j = 0; j < 4; j++) {
            if (i0 + j < N_NODES) {
                int c = g_cursor[i0 + j] + off;
                g_cursor[i0 + j] = c;
                g_rowptr[i0 + j] = c;
                g_deg[i0 + j] = 0;
            }
        }
    }
    if (blockIdx.x == 0 && tid == 0) g_rowptr[N_NODES] = N_EDGES;
}

// 4 edges per thread
__global__ void k_scatter(const int* __restrict__ ei) {
    int e = (blockIdx.x * blockDim.x + threadIdx.x) * 4;
    if (e >= N_EDGES) return;
    int4 d = *(const int4*)&ei[N_EDGES + e];
    int4 s = *(const int4*)&ei[e];
    int p0 = atomicAdd(&g_cursor[d.x], 1);
    int p1 = atomicAdd(&g_cursor[d.y], 1);
    int p2 = atomicAdd(&g_cursor[d.z], 1);
    int p3 = atomicAdd(&g_cursor[d.w], 1);
    g_csrsrc[p0] = s.x;
    g_csrsrc[p1] = s.y;
    g_csrsrc[p2] = s.z;
    g_csrsrc[p3] = s.w;
}

// ---------------- layer-0 input GEMM: g_y = x[N,128] @ W1_0[128,64] (TF32) ----
__global__ __launch_bounds__(256) void k_gemm0(const float* __restrict__ A,
                                               const float* __restrict__ W) {
    constexpr int K = 128;
    __shared__ unsigned sA[256 * 17];
    __shared__ unsigned sW[16 * 65];
    int tid = threadIdx.x;
    int wid = tid >> 5, lane = tid & 31;
    int tg = lane >> 2, tig = lane & 3;
    int row0 = blockIdx.x * 256;

    float c[2][8][4];
    #pragma unroll
    for (int mt = 0; mt < 2; mt++)
        #pragma unroll
        for (int nt = 0; nt < 8; nt++)
            #pragma unroll
            for (int j = 0; j < 4; j++) c[mt][nt][j] = 0.f;

    for (int ch = 0; ch < 8; ch++) {
        int kbase = ch * 16;
        #pragma unroll
        for (int i = 0; i < 4; i++) {
            int idx = tid + i * 256;
            int r = idx >> 2, c4 = idx & 3;
            int grow = row0 + r;
            float4 v = make_float4(0.f, 0.f, 0.f, 0.f);
            if (grow < N_NODES)
                v = *(const float4*)(A + (size_t)grow * K + kbase + c4 * 4);
            unsigned* p = &sA[r * 17 + c4 * 4];
            p[0] = f2tf(v.x); p[1] = f2tf(v.y); p[2] = f2tf(v.z); p[3] = f2tf(v.w);
        }
        {
            int k = tid >> 4, c4 = tid & 15;
            float4 v = *(const float4*)(W + (size_t)(kbase + k) * 64 + c4 * 4);
            unsigned* p = &sW[k * 65 + c4 * 4];
            p[0] = f2tf(v.x); p[1] = f2tf(v.y); p[2] = f2tf(v.z); p[3] = f2tf(v.w);
        }
        __syncthreads();
        #pragma unroll
        for (int ks = 0; ks < 2; ks++) {
            int ko = ks * 8;
            unsigned a[2][4];
            #pragma unroll
            for (int mt = 0; mt < 2; mt++) {
                int rr = wid * 32 + mt * 16 + tg;
                a[mt][0] = sA[rr * 17 + ko + tig];
                a[mt][1] = sA[(rr + 8) * 17 + ko + tig];
                a[mt][2] = sA[rr * 17 + ko + tig + 4];
                a[mt][3] = sA[(rr + 8) * 17 + ko + tig + 4];
            }
            #pragma unroll
            for (int nt = 0; nt < 8; nt++) {
                unsigned b0 = sW[(ko + tig) * 65 + nt * 8 + tg];
                unsigned b1 = sW[(ko + tig + 4) * 65 + nt * 8 + tg];
                mma_tf32(c[0][nt], a[0], b0, b1);
                mma_tf32(c[1][nt], a[1], b0, b1);
            }
        }
        __syncthreads();
    }
    #pragma unroll
    for (int mt = 0; mt < 2; mt++) {
        int row = row0 + wid * 32 + mt * 16 + tg;
        #pragma unroll
        for (int half_i = 0; half_i < 2; half_i++) {
            int r = row + half_i * 8;
            if (r < N_NODES) {
                #pragma unroll
                for (int nt = 0; nt < 8; nt++) {
                    int col = nt * 8 + tig * 2;
                    *(__half2*)(g_y + (size_t)r * HD + col) =
                        __float22half2_rn(make_float2(c[mt][nt][half_i * 2 + 0],
                                                      c[mt][nt][half_i * 2 + 1]));
                }
            }
        }
    }
}

// ---------------- chained dual GEMM, fp16 MMA ----------------
// sA: 128 rows x 64 halves (stride 72); sWT: W transposed [n][k] fp16 (stride 72).
// GEMM: m16n8k16, A row-major from sA, B col-major from sWT.
template <bool DUAL>
__global__ __launch_bounds__(128) void k_dual(const float* __restrict__ W2,
                                              const float* __restrict__ W1n,
                                              const int* __restrict__ batch) {
    __shared__ __half sA[128 * 72];
    __shared__ __half sWT[64 * 72];

    int tid = threadIdx.x, wid = tid >> 5, lane = tid & 31;
    int tg = lane >> 2, tig = lane & 3;
    int row0 = blockIdx.x * 128;

    // load A rows (fp16, no conversion) + stage W2^T
    #pragma unroll
    for (int i = 0; i < 8; i++) {
        int idx = tid + i * 128;
        int r = idx >> 3, seg = idx & 7;
        int grow = row0 + r;
        uint4 raw = make_uint4(0u, 0u, 0u, 0u);
        if (grow < N_NODES)
            raw = *(const uint4*)(g_a + (size_t)grow * HD + seg * 8);
        *(uint4*)&sA[r * 72 + seg * 8] = raw;
    }
    #pragma unroll
    for (int i = 0; i < 32; i++) {
        int idx = i * 128 + tid;
        int k = idx >> 6, n = idx & 63;
        sWT[n * 72 + k] = __float2half(W2[idx]);
    }
    __syncthreads();

    float c[2][8][4];
    #pragma unroll
    for (int mt = 0; mt < 2; mt++)
        #pragma unroll
        for (int nt = 0; nt < 8; nt++)
            #pragma unroll
            for (int j = 0; j < 4; j++) c[mt][nt][j] = 0.f;

    // ---- GEMM1: A @ W2 (4 k16-steps) ----
    #pragma unroll
    for (int ks = 0; ks < 4; ks++) {
        int kg = ks * 16;
        unsigned a[2][4];
        #pragma unroll
        for (int mt = 0; mt < 2; mt++) {
            int rr = wid * 32 + mt * 16 + tg;
            a[mt][0] = *(unsigned*)&sA[rr * 72 + kg + 2 * tig];
            a[mt][1] = *(unsigned*)&sA[(rr + 8) * 72 + kg + 2 * tig];
            a[mt][2] = *(unsigned*)&sA[rr * 72 + kg + 2 * tig + 8];
            a[mt][3] = *(unsigned*)&sA[(rr + 8) * 72 + kg + 2 * tig + 8];
        }
        #pragma unroll
        for (int nt = 0; nt < 8; nt++) {
            unsigned b0 = *(unsigned*)&sWT[(nt * 8 + tg) * 72 + kg + 2 * tig];
            unsigned b1 = *(unsigned*)&sWT[(nt * 8 + tg) * 72 + kg + 2 * tig + 8];
            mma_f16(c[0][nt], a[0], b0, b1);
            mma_f16(c[1][nt], a[1], b0, b1);
        }
    }

    if (!DUAL) {
        #pragma unroll
        for (int mt = 0; mt < 2; mt++) {
            int row = row0 + wid * 32 + mt * 16 + tg;
            #pragma unroll
            for (int half_i = 0; half_i < 2; half_i++) {
                int r = row + half_i * 8;
                if (r < N_NODES) {
                    int b = batch[r];
                    #pragma unroll
                    for (int nt = 0; nt < 8; nt++) {
                        int col = nt * 8 + tig * 2;
                        atomicAdd(&g_pool[b * HD + col],
                                  fmaxf(c[mt][nt][half_i * 2 + 0], 0.f));
                        atomicAdd(&g_pool[b * HD + col + 1],
                                  fmaxf(c[mt][nt][half_i * 2 + 1], 0.f));
                    }
                }
            }
        }
        return;
    }

    // ---- relu + write h back into sA (warp-private rows, fp16) ----
    #pragma unroll
    for (int mt = 0; mt < 2; mt++) {
        int rlo = wid * 32 + mt * 16 + tg;
        #pragma unroll
        for (int nt = 0; nt < 8; nt++) {
            int col = nt * 8 + 2 * tig;
            *(__half2*)&sA[rlo * 72 + col] =
                __float22half2_rn(make_float2(fmaxf(c[mt][nt][0], 0.f),
                                              fmaxf(c[mt][nt][1], 0.f)));
            *(__half2*)&sA[(rlo + 8) * 72 + col] =
                __float22half2_rn(make_float2(fmaxf(c[mt][nt][2], 0.f),
                                              fmaxf(c[mt][nt][3], 0.f)));
        }
    }
    __syncthreads();   // all warps done reading sWT(W2) and writing h

    // stage W1n^T
    #pragma unroll
    for (int i = 0; i < 32; i++) {
        int idx = i * 128 + tid;
        int k = idx >> 6, n = idx & 63;
        sWT[n * 72 + k] = __float2half(W1n[idx]);
    }
    __syncthreads();

    #pragma unroll
    for (int mt = 0; mt < 2; mt++)
        #pragma unroll
        for (int nt = 0; nt < 8; nt++)
            #pragma unroll
            for (int j = 0; j < 4; j++) c[mt][nt][j] = 0.f;

    // ---- GEMM2: h @ W1next ----
    #pragma unroll
    for (int ks = 0; ks < 4; ks++) {
        int kg = ks * 16;
        unsigned a[2][4];
        #pragma unroll
        for (int mt = 0; mt < 2; mt++) {
            int rr = wid * 32 + mt * 16 + tg;
            a[mt][0] = *(unsigned*)&sA[rr * 72 + kg + 2 * tig];
            a[mt][1] = *(unsigned*)&sA[(rr + 8) * 72 + kg + 2 * tig];
            a[mt][2] = *(unsigned*)&sA[rr * 72 + kg + 2 * tig + 8];
            a[mt][3] = *(unsigned*)&sA[(rr + 8) * 72 + kg + 2 * tig + 8];
        }
        #pragma unroll
        for (int nt = 0; nt < 8; nt++) {
            unsigned b0 = *(unsigned*)&sWT[(nt * 8 + tg) * 72 + kg + 2 * tig];
            unsigned b1 = *(unsigned*)&sWT[(nt * 8 + tg) * 72 + kg + 2 * tig + 8];
            mma_f16(c[0][nt], a[0], b0, b1);
            mma_f16(c[1][nt], a[1], b0, b1);
        }
    }

    // store y (no relu)
    #pragma unroll
    for (int mt = 0; mt < 2; mt++) {
        int row = row0 + wid * 32 + mt * 16 + tg;
        #pragma unroll
        for (int half_i = 0; half_i < 2; half_i++) {
            int r = row + half_i * 8;
            if (r < N_NODES) {
                #pragma unroll
                for (int nt = 0; nt < 8; nt++) {
                    int col = nt * 8 + tig * 2;
                    *(__half2*)(g_y + (size_t)r * HD + col) =
                        __float22half2_rn(make_float2(c[mt][nt][half_i * 2 + 0],
                                                      c[mt][nt][half_i * 2 + 1]));
                }
            }
        }
    }
}

// ---------------- aggregation + BN + relu: FOUR nodes per warp ----------------
__global__ __launch_bounds__(256) void k_agg(const float* __restrict__ gam,
                                             const float* __restrict__ bet,
                                             const float* __restrict__ mea,
                                             const float* __restrict__ var) {
    __shared__ float sScale[64], sShift[64];
    int tid = threadIdx.x;
    if (tid < 64) {
        float sc = rsqrtf(var[tid] + BN_EPS) * gam[tid];
        sScale[tid] = sc;
        sShift[tid] = bet[tid] - mea[tid] * sc;
    }
    __syncthreads();

    int gw = (blockIdx.x * 256 + tid) >> 5;
    if (gw >= N_NODES / 4) return;
    int lane = tid & 31;
    int q = lane >> 3;
    int sub = lane & 7;
    int node = 4 * gw + q;

    const uint4* yv = (const uint4*)g_y;

    float a[8];
    {
        uint4 raw = yv[(size_t)node * 8 + sub];
        float2 f0 = __half22float2(*(__half2*)&raw.x);
        float2 f1 = __half22float2(*(__half2*)&raw.y);
        float2 f2 = __half22float2(*(__half2*)&raw.z);
        float2 f3 = __half22float2(*(__half2*)&raw.w);
        a[0] = f0.x; a[1] = f0.y; a[2] = f1.x; a[3] = f1.y;
        a[4] = f2.x; a[5] = f2.y; a[6] = f3.x; a[7] = f3.y;
    }

    int b = g_rowptr[node];
    int end = g_rowptr[node + 1];

    while (__any_sync(0xffffffffu, b < end)) {
        int n = end - b;
        if (n > 8) n = 8;
        if (n < 0) n = 0;
        int idx = (sub < n) ? g_csrsrc[b + sub] : 0;
        int m = n;
        m = max(m, __shfl_xor_sync(0xffffffffu, m, 8));
        m = max(m, __shfl_xor_sync(0xffffffffu, m, 16));
        int srcbase = q * 8;
        int t = 0;
        for (; t + 4 <= m; t += 4) {
            int s0 = __shfl_sync(0xffffffffu, idx, srcbase + t + 0);
            int s1 = __shfl_sync(0xffffffffu, idx, srcbase + t + 1);
            int s2 = __shfl_sync(0xffffffffu, idx, srcbase + t + 2);
            int s3 = __shfl_sync(0xffffffffu, idx, srcbase + t + 3);
            uint4 r0 = yv[(size_t)s0 * 8 + sub];
            uint4 r1 = yv[(size_t)s1 * 8 + sub];
            uint4 r2 = yv[(size_t)s2 * 8 + sub];
            uint4 r3 = yv[(size_t)s3 * 8 + sub];
            if (t + 0 < n) {
                float2 u0 = __half22float2(*(__half2*)&r0.x);
                float2 u1 = __half22float2(*(__half2*)&r0.y);
                float2 u2 = __half22float2(*(__half2*)&r0.z);
                float2 u3 = __half22float2(*(__half2*)&r0.w);
                a[0] += u0.x; a[1] += u0.y; a[2] += u1.x; a[3] += u1.y;
                a[4] += u2.x; a[5] += u2.y; a[6] += u3.x; a[7] += u3.y;
            }
            if (t + 1 < n) {
                float2 u0 = __half22float2(*(__half2*)&r1.x);
                float2 u1 = __half22float2(*(__half2*)&r1.y);
                float2 u2 = __half22float2(*(__half2*)&r1.z);
                float2 u3 = __half22float2(*(__half2*)&r1.w);
                a[0] += u0.x; a[1] += u0.y; a[2] += u1.x; a[3] += u1.y;
                a[4] += u2.x; a[5] += u2.y; a[6] += u3.x; a[7] += u3.y;
            }
            if (t + 2 < n) {
                float2 u0 = __half22float2(*(__half2*)&r2.x);
                float2 u1 = __half22float2(*(__half2*)&r2.y);
                float2 u2 = __half22float2(*(__half2*)&r2.z);
                float2 u3 = __half22float2(*(__half2*)&r2.w);
                a[0] += u0.x; a[1] += u0.y; a[2] += u1.x; a[3] += u1.y;
                a[4] += u2.x; a[5] += u2.y; a[6] += u3.x; a[7] += u3.y;
            }
            if (t + 3 < n) {
                float2 u0 = __half22float2(*(__half2*)&r3.x);
                float2 u1 = __half22float2(*(__half2*)&r3.y);
                float2 u2 = __half22float2(*(__half2*)&r3.z);
                float2 u3 = __half22float2(*(__half2*)&r3.w);
                a[0] += u0.x; a[1] += u0.y; a[2] += u1.x; a[3] += u1.y;
                a[4] += u2.x; a[5] += u2.y; a[6] += u3.x; a[7] += u3.y;
            }
        }
        for (; t < m; t++) {
            int s = __shfl_sync(0xffffffffu, idx, srcbase + t);
            uint4 r = yv[(size_t)s * 8 + sub];
            if (t < n) {
                float2 u0 = __half22float2(*(__half2*)&r.x);
                float2 u1 = __half22float2(*(__half2*)&r.y);
                float2 u2 = __half22float2(*(__half2*)&r.z);
                float2 u3 = __half22float2(*(__half2*)&r.w);
                a[0] += u0.x; a[1] += u0.y; a[2] += u1.x; a[3] += u1.y;
                a[4] += u2.x; a[5] += u2.y; a[6] += u3.x; a[7] += u3.y;
            }
        }
        b += 8;
    }

    int c0 = sub * 8;
    float4 scA = *(float4*)&sScale[c0];
    float4 scB = *(float4*)&sScale[c0 + 4];
    float4 shA = *(float4*)&sShift[c0];
    float4 shB = *(float4*)&sShift[c0 + 4];
    float h0 = fmaxf(fmaf(a[0], scA.x, shA.x), 0.f);
    float h1 = fmaxf(fmaf(a[1], scA.y, shA.y), 0.f);
    float h2 = fmaxf(fmaf(a[2], scA.z, shA.z), 0.f);
    float h3 = fmaxf(fmaf(a[3], scA.w, shA.w), 0.f);
    float h4 = fmaxf(fmaf(a[4], scB.x, shB.x), 0.f);
    float h5 = fmaxf(fmaf(a[5], scB.y, shB.y), 0.f);
    float h6 = fmaxf(fmaf(a[6], scB.z, shB.z), 0.f);
    float h7 = fmaxf(fmaf(a[7], scB.w, shB.w), 0.f);
    uint4 outv;
    *(__half2*)&outv.x = __float22half2_rn(make_float2(h0, h1));
    *(__half2*)&outv.y = __float22half2_rn(make_float2(h2, h3));
    *(__half2*)&outv.z = __float22half2_rn(make_float2(h4, h5));
    *(__half2*)&outv.w = __float22half2_rn(make_float2(h6, h7));
    ((uint4*)g_a)[(size_t)node * 8 + sub] = outv;
}

// ---------------- final head (self-cleans g_pool / g_cnt) ----------------
__global__ void k_final(const float* __restrict__ lin1, const float* __restrict__ lin2,
                        const float* __restrict__ lb, float* __restrict__ out) {
    __shared__ float sL1[64 * 64];
    __shared__ float sL2[64 * 10];
    __shared__ float sB[10];
    int tid = threadIdx.x;
    for (int i = tid; i < 64 * 64; i += 128) sL1[i] = lin1[i];
    for (int i = tid; i < 64 * 10; i += 128) sL2[i] = lin2[i];
    if (tid < 10) sB[tid] = lb[tid];
    __syncthreads();
    if (tid < N_GRAPHS) {
        float cnt = (float)g_cnt[tid];
        if (cnt < 1.f) cnt = 1.f;
        float pooled[64];
        #pragma unroll
        for (int k = 0; k < 64; k++) {
            pooled[k] = g_pool[tid * 64 + k] / cnt;
            g_pool[tid * 64 + k] = 0.f;
        }
        g_cnt[tid] = 0;
        float o[10];
        #pragma unroll
        for (int c = 0; c < 10; c++) o[c] = sB[c];
        for (int j = 0; j < 64; j++) {
            float z = 0.f;
            #pragma unroll
            for (int k = 0; k < 64; k++) z += pooled[k] * sL1[k * 64 + j];
            z = fmaxf(z, 0.f);
            #pragma unroll
            for (int c = 0; c < 10; c++) o[c] += z * sL2[j * 10 + c];
        }
        float mx = o[0];
        #pragma unroll
        for (int c = 1; c < 10; c++) mx = fmaxf(mx, o[c]);
        float se = 0.f;
        #pragma unroll
        for (int c = 0; c < 10; c++) se += expf(o[c] - mx);
        float lse = logf(se) + mx;
        #pragma unroll
        for (int c = 0; c < 10; c++) out[tid * 10 + c] = o[c] - lse;
    }
}

// ---------------- launch ----------------
extern "C" void kernel_launch(void* const* d_in, const int* in_sizes, int n_in,
                              void* d_out, int out_size) {
    const float* x      = (const float*)d_in[0];
    const int*   ei     = (const int*)d_in[1];
    const int*   batch  = (const int*)d_in[2];
    const float* W1_0   = (const float*)d_in[3];
    const float* bn_g_0 = (const float*)d_in[4];
    const float* bn_b_0 = (const float*)d_in[5];
    const float* bn_m_0 = (const float*)d_in[6];
    const float* bn_v_0 = (const float*)d_in[7];
    const float* W2_0   = (const float*)d_in[8];
    const float* W1_r   = (const float*)d_in[9];
    const float* bn_g_r = (const float*)d_in[10];
    const float* bn_b_r = (const float*)d_in[11];
    const float* bn_m_r = (const float*)d_in[12];
    const float* bn_v_r = (const float*)d_in[13];
    const float* W2_r   = (const float*)d_in[14];
    const float* lin1   = (const float*)d_in[15];
    const float* lin2   = (const float*)d_in[16];
    const float* lin2b  = (const float*)d_in[17];
    float* out = (float*)d_out;

    const int TPB = 256;
    int gridEdges4 = (N_EDGES / 4 + TPB - 1) / TPB;      // 977
    int gridGemm0 = (N_NODES + 255) / 256;               // 391
    int gridDual = (N_NODES + 127) / 128;                // 782
    int gridAgg = ((N_NODES / 4) * 32 + TPB - 1) / TPB;  // 3125

    cudaStream_t side;
    cudaStreamCreateWithFlags(&side, cudaStreamNonBlocking);
    cudaEvent_t evFork, evJoin;
    cudaEventCreateWithFlags(&evFork, cudaEventDisableTiming);
    cudaEventCreateWithFlags(&evJoin, cudaEventDisableTiming);

    cudaEventRecord(evFork, 0);
    cudaStreamWaitEvent(side, evFork, 0);
    k_gemm0<<<gridGemm0, TPB, 0, side>>>(x, W1_0);     // y0 = x @ W1_0
    cudaEventRecord(evJoin, side);

    k_count<<<gridEdges4, TPB>>>(ei, batch);
    k_scan1<<<SCAN_BLK, 1024>>>();
    k_scan23<<<SCAN_BLK, 1024>>>();
    k_scatter<<<gridEdges4, TPB>>>(ei);

    cudaStreamWaitEvent(0, evJoin, 0);

    k_agg<<<gridAgg, TPB>>>(bn_g_0, bn_b_0, bn_m_0, bn_v_0);
    k_dual<true><<<gridDual, 128>>>(W2_0, W1_r + 0 * 4096, nullptr);
    k_agg<<<gridAgg, TPB>>>(bn_g_r + 0, bn_b_r + 0, bn_m_r + 0, bn_v_r + 0);
    k_dual<true><<<gridDual, 128>>>(W2_r + 0 * 4096, W1_r + 1 * 4096, nullptr);
    k_agg<<<gridAgg, TPB>>>(bn_g_r + 64, bn_b_r + 64, bn_m_r + 64, bn_v_r + 64);
    k_dual<true><<<gridDual, 128>>>(W2_r + 1 * 4096, W1_r + 2 * 4096, nullptr);
    k_agg<<<gridAgg, TPB>>>(bn_g_r + 128, bn_b_r + 128, bn_m_r + 128, bn_v_r + 128);
    k_dual<false><<<gridDual, 128>>>(W2_r + 2 * 4096, nullptr, batch);

    k_final<<<1, 128>>>(lin1, lin2, lin2b, out);

    cudaStreamDestroy(side);
    cudaEventDestroy(evFork);
    cudaEventDestroy(evJoin);
}